// round 1
// baseline (speedup 1.0000x reference)
#include <cuda_runtime.h>
#include <math.h>

// ---------------------------------------------------------------------------
// STGNN: Cheb-KNN graph conv (K=3, top-8) -> GRU(hidden 64, L=32) -> FC
// Shapes: bs=256, N=64, T=2048, patch=64, L=32, hidden=64, M=bs*L=8192,
//         sequences = bs*N = 16384.
// ---------------------------------------------------------------------------

#define DEV static __device__ __forceinline__

// scratch (device globals: allocation-free rule)
__device__ float g_g[16384 * 32 * 64];    // g: [seq=16384][l=32][h=64] (128MB)
__device__ float g_gi[524288 * 192];      // gi: [seq*32+l][192]        (384MB)
__device__ float g_part[1024];            // per-block FC partials

DEV float f4get(const float4 v, int c) {
    return c == 0 ? v.x : (c == 1 ? v.y : (c == 2 ? v.z : v.w));
}

// C[i0..i0+3][j0..j0+3] += A[i][f] * B[f][j], K=64. A stride LDA, B stride LDB.
template <int LDA, int LDB>
DEV void mm64(const float* A, const float* B, float (&acc)[4][4], int i0, int j0) {
#pragma unroll 4
    for (int f = 0; f < 64; f += 4) {
        float4 a[4], bb[4];
#pragma unroll
        for (int r = 0; r < 4; r++)
            a[r] = *(const float4*)(A + (i0 + r) * LDA + f);
#pragma unroll
        for (int k = 0; k < 4; k++)
            bb[k] = *(const float4*)(B + (f + k) * LDB + j0);
#pragma unroll
        for (int r = 0; r < 4; r++) {
#pragma unroll
            for (int c = 0; c < 4; c++) {
                acc[r][c] += a[r].x * f4get(bb[0], c);
                acc[r][c] += a[r].y * f4get(bb[1], c);
                acc[r][c] += a[r].z * f4get(bb[2], c);
                acc[r][c] += a[r].w * f4get(bb[3], c);
            }
        }
    }
}

DEV void zero44(float (&a)[4][4]) {
#pragma unroll
    for (int r = 0; r < 4; r++)
#pragma unroll
        for (int c = 0; c < 4; c++) a[r][c] = 0.f;
}

// ---------------------------------------------------------------------------
// Kernel 1: per-m Cheb graph conv. grid=8192, block=256.
// smem: xs[64*64] xsT[64*68] adj[64*64] t1[64*64] fs[2*64*64] sq[64]
// ---------------------------------------------------------------------------
__global__ void __launch_bounds__(256) k1_cheb(const float* __restrict__ x,
                                               const float* __restrict__ filters) {
    extern __shared__ __align__(16) float sm1[];
    float* xs  = sm1;            // 4096
    float* xsT = sm1 + 4096;     // 4352 (stride 68; later holds Tn)
    float* adj = sm1 + 8448;     // 4096 (Gram -> sim -> adj)
    float* t1  = sm1 + 12544;    // 4096 (Tx1)
    float* fs  = sm1 + 16640;    // 8192 (F0,F1; F0 slot later F2)
    float* sq  = sm1 + 24832;    // 64

    const int m = blockIdx.x;
    const int b = m >> 5, l = m & 31;
    const int tid = threadIdx.x;

    // load xf[n][f] = x[(b*64+n)*2048 + l*64 + f]
    const float* xb = x + (size_t)b * 64 * 2048 + l * 64;
#pragma unroll
    for (int k = 0; k < 4; k++) {
        int v = tid + k * 256;            // 0..1023 float4 slots
        int n = v >> 4, fo = (v & 15) << 2;
        *(float4*)(xs + n * 64 + fo) = *(const float4*)(xb + (size_t)n * 2048 + fo);
    }
    // load F0, F1
    for (int i = tid; i < 8192; i += 256) fs[i] = filters[i];
    __syncthreads();

    // transpose: xsT[f*68+n] = xs[n*64+f]
    for (int i = tid; i < 4096; i += 256) {
        int n = i >> 6, f = i & 63;
        xsT[f * 68 + n] = xs[i];
    }
    __syncthreads();

    const int tr = tid >> 4, tc = tid & 15;
    const int i0 = tr << 2, j0 = tc << 2;

    float acc[4][4];

    // Gram = xs @ xs^T
    zero44(acc);
    mm64<64, 68>(xs, xsT, acc, i0, j0);
#pragma unroll
    for (int r = 0; r < 4; r++)
        *(float4*)(adj + (i0 + r) * 64 + j0) =
            make_float4(acc[r][0], acc[r][1], acc[r][2], acc[r][3]);
    __syncthreads();

    if (tid < 64) sq[tid] = adj[tid * 64 + tid];
    __syncthreads();

    // sim = exp(-max(sq_i + sq_j - 2*Gram, 0))
    for (int i = tid; i < 4096; i += 256) {
        int r = i >> 6, c = i & 63;
        float d2 = sq[r] + sq[c] - 2.f * adj[i];
        adj[i] = expf(-fmaxf(d2, 0.f));
    }
    __syncthreads();

    // top-8 per row (ties: earliest index, matching jax top_k)
    if (tid < 64) {
        float* row = adj + tid * 64;
        float tk[8];
#pragma unroll
        for (int i = 0; i < 8; i++) tk[i] = -1.f;
        for (int j = 0; j < 64; j++) {
            float v = row[j];
#pragma unroll
            for (int i = 0; i < 8; i++) {
                float mx = fmaxf(tk[i], v);
                v = fminf(tk[i], v);
                tk[i] = mx;
            }
        }
        float thr = tk[7];
        int cg = 0;
        for (int j = 0; j < 64; j++) cg += (row[j] > thr) ? 1 : 0;
        int rem = 8 - cg;
        for (int j = 0; j < 64; j++) {
            float v = row[j];
            if (v > thr) continue;
            if (v == thr && rem > 0) { rem--; continue; }
            row[j] = 0.f;
        }
    }
    __syncthreads();

    // Tx1 = adj @ xs
    zero44(acc);
    mm64<64, 64>(adj, xs, acc, i0, j0);
#pragma unroll
    for (int r = 0; r < 4; r++)
        *(float4*)(t1 + (i0 + r) * 64 + j0) =
            make_float4(acc[r][0], acc[r][1], acc[r][2], acc[r][3]);
    __syncthreads();

    // out = xs @ F0 + Tx1 @ F1
    float outa[4][4];
    zero44(outa);
    mm64<64, 64>(xs, fs, outa, i0, j0);
    mm64<64, 64>(t1, fs + 4096, outa, i0, j0);
    __syncthreads();   // done reading F0 slot

    // F2 into F0 slot;  Tn = 2*adj@Tx1 - xs  -> xsT buffer (stride 68)
    for (int i = tid; i < 4096; i += 256) fs[i] = filters[8192 + i];
    zero44(acc);
    mm64<64, 64>(adj, t1, acc, i0, j0);
#pragma unroll
    for (int r = 0; r < 4; r++) {
        float4 xv = *(const float4*)(xs + (i0 + r) * 64 + j0);
        float4 tn;
        tn.x = 2.f * acc[r][0] - xv.x;
        tn.y = 2.f * acc[r][1] - xv.y;
        tn.z = 2.f * acc[r][2] - xv.z;
        tn.w = 2.f * acc[r][3] - xv.w;
        *(float4*)(xsT + (i0 + r) * 68 + j0) = tn;
    }
    __syncthreads();

    // out += Tn @ F2
    mm64<68, 64>(xsT, fs, outa, i0, j0);

    // store g[(b*64+n)*32 + l][h]
#pragma unroll
    for (int r = 0; r < 4; r++) {
        size_t o = (((size_t)b * 64 + i0 + r) * 32 + l) * 64 + j0;
        *(float4*)(g_g + o) = make_float4(outa[r][0], outa[r][1], outa[r][2], outa[r][3]);
    }
}

// ---------------------------------------------------------------------------
// Kernel 2a: gi = g @ w_ih^T + b_ih.  grid=(8192,3), block=256.
// Each block: 64 rows x one 64-col panel of the 192 outputs.
// ---------------------------------------------------------------------------
__global__ void __launch_bounds__(256) k2a_gi(const float* __restrict__ w_ih,
                                              const float* __restrict__ b_ih) {
    __shared__ __align__(16) float As[4096];      // 64 rows x 64 f
    __shared__ __align__(16) float Bs[64 * 68];   // w_ih^T panel [f][j], stride 68

    const int tid = threadIdx.x;
    const int rb = blockIdx.x;       // row block (64 rows each)
    const int panel = blockIdx.y;    // 0..2

    const float* src = g_g + (size_t)rb * 4096;
#pragma unroll
    for (int k = 0; k < 4; k++) {
        int v = (tid + k * 256) << 2;
        *(float4*)(As + v) = *(const float4*)(src + v);
    }
    for (int i = tid; i < 4096; i += 256) {
        int row = i >> 6, f = i & 63;  // coalesced global read, 4-way smem write
        Bs[f * 68 + row] = w_ih[(panel * 64 + row) * 64 + f];
    }
    __syncthreads();

    const int tr = tid >> 4, tc = tid & 15;
    const int i0 = tr << 2, j0 = tc << 2;
    float acc[4][4];
    zero44(acc);
    mm64<64, 68>(As, Bs, acc, i0, j0);

    const float4 bi = *(const float4*)(b_ih + panel * 64 + j0);
#pragma unroll
    for (int r = 0; r < 4; r++) {
        size_t o = ((size_t)rb * 64 + i0 + r) * 192 + panel * 64 + j0;
        *(float4*)(g_gi + o) = make_float4(acc[r][0] + bi.x, acc[r][1] + bi.y,
                                           acc[r][2] + bi.z, acc[r][3] + bi.w);
    }
}

// ---------------------------------------------------------------------------
// Kernel 2b: GRU recurrence + fused FC dot.  grid=1024 (16 seqs each), block=192.
// smem: wT[64*196] gates[16*256] hs[16*64] bhh[192]
// ---------------------------------------------------------------------------
__global__ void __launch_bounds__(192) k2b_gru(const float* __restrict__ w_hh,
                                               const float* __restrict__ b_hh,
                                               const float* __restrict__ fc_w) {
    extern __shared__ __align__(16) float sm2[];
    float* wT    = sm2;             // 12544 (stride 196)
    float* gates = sm2 + 12544;     // 4096: [s][0:64)=r, [64:128)=z, [128:192)=i_n, [192:256)=h_n
    float* hs    = sm2 + 16640;     // 1024
    float* bhh   = sm2 + 17664;     // 192

    const int tid = threadIdx.x;
    const int seq0 = blockIdx.x * 16;
    const int n0 = seq0 & 63;       // node offset within batch

    for (int i = tid; i < 12288; i += 192) {
        int row = i >> 6, f = i & 63;
        wT[f * 196 + row] = w_hh[i];
    }
    bhh[tid] = b_hh[tid];
    for (int i = tid; i < 1024; i += 192) hs[i] = 0.f;
    __syncthreads();

    const int cg = tid % 48, sr = tid / 48;
    const int s0 = sr * 4, c0 = cg * 4;
    float fcacc = 0.f;

    for (int l = 0; l < 32; l++) {
        // gh tile = hs[s0..+3][:] @ w_hh^T[:, c0..+3]
        float acc[4][4];
        zero44(acc);
        mm64<64, 196>(hs, wT, acc, s0, c0);

        const float4 bh4 = *(const float4*)(bhh + c0);
#pragma unroll
        for (int s = 0; s < 4; s++) {
            const int sl = s0 + s;
            const float4 gi4 =
                *(const float4*)(g_gi + ((size_t)(seq0 + sl) * 32 + l) * 192 + c0);
            if (c0 < 128) {
                float4 o;
                o.x = acc[s][0] + bh4.x + gi4.x;
                o.y = acc[s][1] + bh4.y + gi4.y;
                o.z = acc[s][2] + bh4.z + gi4.z;
                o.w = acc[s][3] + bh4.w + gi4.w;
                *(float4*)(gates + sl * 256 + c0) = o;
            } else {
                float4 hn4;
                hn4.x = acc[s][0] + bh4.x;
                hn4.y = acc[s][1] + bh4.y;
                hn4.z = acc[s][2] + bh4.z;
                hn4.w = acc[s][3] + bh4.w;
                *(float4*)(gates + sl * 256 + c0 + 64) = hn4;   // h_n
                *(float4*)(gates + sl * 256 + c0) = gi4;        // i_n
            }
        }
        __syncthreads();

        // gate math + h update + fused FC accumulation
        for (int i = tid; i < 1024; i += 192) {
            int s = i >> 6, j = i & 63;
            const float* gp = gates + s * 256 + j;
            float rg = 1.f / (1.f + expf(-gp[0]));
            float zg = 1.f / (1.f + expf(-gp[64]));
            float ng = tanhf(gp[128] + rg * gp[192]);
            float h = hs[s * 64 + j];
            float hn = (1.f - zg) * ng + zg * h;
            hs[s * 64 + j] = hn;
            fcacc += hn * fc_w[(n0 + s) * 2048 + l * 64 + j];
        }
        __syncthreads();
    }

    // block reduce fcacc (deterministic)
#pragma unroll
    for (int o = 16; o > 0; o >>= 1)
        fcacc += __shfl_down_sync(0xffffffffu, fcacc, o);
    float* red = gates;
    if ((tid & 31) == 0) red[tid >> 5] = fcacc;
    __syncthreads();
    if (tid == 0) {
        float s = 0.f;
#pragma unroll
        for (int w = 0; w < 6; w++) s += red[w];
        g_part[blockIdx.x] = s;
    }
}

// ---------------------------------------------------------------------------
// Kernel 3: out[b] = fc_b + sum of 4 block partials
// ---------------------------------------------------------------------------
__global__ void k3_fc(const float* __restrict__ fc_b, float* __restrict__ out) {
    int b = threadIdx.x;  // 256
    float s = fc_b[0];
#pragma unroll
    for (int k = 0; k < 4; k++) s += g_part[b * 4 + k];
    out[b] = s;
}

// ---------------------------------------------------------------------------
extern "C" void kernel_launch(void* const* d_in, const int* in_sizes, int n_in,
                              void* d_out, int out_size) {
    const float* x    = (const float*)d_in[0];
    const float* filt = (const float*)d_in[1];
    const float* w_ih = (const float*)d_in[2];
    const float* w_hh = (const float*)d_in[3];
    const float* b_ih = (const float*)d_in[4];
    const float* b_hh = (const float*)d_in[5];
    const float* fc_w = (const float*)d_in[6];
    const float* fc_b = (const float*)d_in[7];
    float* out = (float*)d_out;

    const int SMEM1 = 24896 * 4;   // 99584 B
    const int SMEM2 = 17856 * 4;   // 71424 B
    cudaFuncSetAttribute(k1_cheb, cudaFuncAttributeMaxDynamicSharedMemorySize, SMEM1);
    cudaFuncSetAttribute(k2b_gru, cudaFuncAttributeMaxDynamicSharedMemorySize, SMEM2);

    k1_cheb<<<8192, 256, SMEM1>>>(x, filt);
    k2a_gi<<<dim3(8192, 3), 256>>>(w_ih, b_ih);
    k2b_gru<<<1024, 192, SMEM2>>>(w_hh, b_hh, fc_w);
    k3_fc<<<1, 256>>>(fc_b, out);
}

// round 2
// speedup vs baseline: 1.0106x; 1.0106x over previous
#include <cuda_runtime.h>
#include <math.h>

// ---------------------------------------------------------------------------
// STGNN: Cheb-KNN graph conv (K=3, top-8) -> GRU(hidden 64, L=32) -> FC
// R2: packed fp32x2 FMA (FFMA2) in all GEMM inner loops -> 2x fp32 roofline.
// ---------------------------------------------------------------------------

#define DEV static __device__ __forceinline__

typedef unsigned long long ull;

// scratch (device globals: allocation-free rule)
__device__ float g_g[16384 * 32 * 64];    // g: [seq=16384][l=32][h=64] (128MB)
__device__ float g_gi[524288 * 192];      // gi: [seq*32+l][192]        (384MB)
__device__ float g_part[1024];            // per-block FC partials

union F4U {
    float4 f;
    ull    u[2];
    float  s[4];
};

DEV ull pack2(float a) {
    ull r;
    asm("mov.b64 %0, {%1, %1};" : "=l"(r) : "r"(__float_as_uint(a)));
    return r;
}

DEV void fma2(ull& acc, ull a, ull b) {
    asm("fma.rn.f32x2 %0, %1, %2, %0;" : "+l"(acc) : "l"(a), "l"(b));
}

// C[i0..i0+3][j0..j0+3] += A[i][f] * B[f][j], K=64, packed pairs along j.
// acc[r][p] holds columns (j0+2p, j0+2p+1). FMA order identical to scalar ref.
template <int LDA, int LDB>
DEV void mm64p(const float* A, const float* B, ull (&acc)[4][2], int i0, int j0) {
#pragma unroll 4
    for (int f = 0; f < 64; f += 4) {
        F4U a[4], bb[4];
#pragma unroll
        for (int r = 0; r < 4; r++)
            a[r].f = *(const float4*)(A + (i0 + r) * LDA + f);
#pragma unroll
        for (int k = 0; k < 4; k++)
            bb[k].f = *(const float4*)(B + (f + k) * LDB + j0);
#pragma unroll
        for (int k = 0; k < 4; k++) {
#pragma unroll
            for (int r = 0; r < 4; r++) {
                ull ad = pack2(a[r].s[k]);
                fma2(acc[r][0], ad, bb[k].u[0]);
                fma2(acc[r][1], ad, bb[k].u[1]);
            }
        }
    }
}

DEV void zacc(ull (&a)[4][2]) {
#pragma unroll
    for (int r = 0; r < 4; r++) { a[r][0] = 0ull; a[r][1] = 0ull; }
}

// ---------------------------------------------------------------------------
// Kernel 1: per-m Cheb graph conv. grid=8192, block=256.
// ---------------------------------------------------------------------------
__global__ void __launch_bounds__(256) k1_cheb(const float* __restrict__ x,
                                               const float* __restrict__ filters) {
    extern __shared__ __align__(16) float sm1[];
    float* xs  = sm1;            // 4096
    float* xsT = sm1 + 4096;     // 4352 (stride 68; later holds Tn)
    float* adj = sm1 + 8448;     // 4096 (Gram -> sim -> adj)
    float* t1  = sm1 + 12544;    // 4096 (Tx1)
    float* fs  = sm1 + 16640;    // 8192 (F0,F1; F0 slot later F2)
    float* sq  = sm1 + 24832;    // 64

    const int m = blockIdx.x;
    const int b = m >> 5, l = m & 31;
    const int tid = threadIdx.x;

    // load xf[n][f] = x[(b*64+n)*2048 + l*64 + f]
    const float* xb = x + (size_t)b * 64 * 2048 + l * 64;
#pragma unroll
    for (int k = 0; k < 4; k++) {
        int v = tid + k * 256;
        int n = v >> 4, fo = (v & 15) << 2;
        *(float4*)(xs + n * 64 + fo) = *(const float4*)(xb + (size_t)n * 2048 + fo);
    }
    for (int i = tid; i < 8192; i += 256) fs[i] = filters[i];
    __syncthreads();

    for (int i = tid; i < 4096; i += 256) {
        int n = i >> 6, f = i & 63;
        xsT[f * 68 + n] = xs[i];
    }
    __syncthreads();

    const int tr = tid >> 4, tc = tid & 15;
    const int i0 = tr << 2, j0 = tc << 2;

    ull acc[4][2];

    // Gram = xs @ xs^T
    zacc(acc);
    mm64p<64, 68>(xs, xsT, acc, i0, j0);
#pragma unroll
    for (int r = 0; r < 4; r++) {
        F4U o; o.u[0] = acc[r][0]; o.u[1] = acc[r][1];
        *(float4*)(adj + (i0 + r) * 64 + j0) = o.f;
    }
    __syncthreads();

    if (tid < 64) sq[tid] = adj[tid * 64 + tid];
    __syncthreads();

    // sim = exp(-max(sq_i + sq_j - 2*Gram, 0))
    for (int i = tid; i < 4096; i += 256) {
        int r = i >> 6, c = i & 63;
        float d2 = sq[r] + sq[c] - 2.f * adj[i];
        adj[i] = expf(-fmaxf(d2, 0.f));
    }
    __syncthreads();

    // top-8 per row (ties: earliest index, matching jax top_k)
    if (tid < 64) {
        float* row = adj + tid * 64;
        float tk[8];
#pragma unroll
        for (int i = 0; i < 8; i++) tk[i] = -1.f;
        for (int j = 0; j < 64; j++) {
            float v = row[j];
#pragma unroll
            for (int i = 0; i < 8; i++) {
                float mx = fmaxf(tk[i], v);
                v = fminf(tk[i], v);
                tk[i] = mx;
            }
        }
        float thr = tk[7];
        int cg = 0;
        for (int j = 0; j < 64; j++) cg += (row[j] > thr) ? 1 : 0;
        int rem = 8 - cg;
        for (int j = 0; j < 64; j++) {
            float v = row[j];
            if (v > thr) continue;
            if (v == thr && rem > 0) { rem--; continue; }
            row[j] = 0.f;
        }
    }
    __syncthreads();

    // Tx1 = adj @ xs
    zacc(acc);
    mm64p<64, 64>(adj, xs, acc, i0, j0);
#pragma unroll
    for (int r = 0; r < 4; r++) {
        F4U o; o.u[0] = acc[r][0]; o.u[1] = acc[r][1];
        *(float4*)(t1 + (i0 + r) * 64 + j0) = o.f;
    }
    __syncthreads();

    // out = xs @ F0 + Tx1 @ F1
    ull outa[4][2];
    zacc(outa);
    mm64p<64, 64>(xs, fs, outa, i0, j0);
    mm64p<64, 64>(t1, fs + 4096, outa, i0, j0);
    __syncthreads();   // done reading F0 slot

    // F2 into F0 slot;  Tn = 2*adj@Tx1 - xs  -> xsT buffer (stride 68)
    for (int i = tid; i < 4096; i += 256) fs[i] = filters[8192 + i];
    zacc(acc);
    mm64p<64, 64>(adj, t1, acc, i0, j0);
#pragma unroll
    for (int r = 0; r < 4; r++) {
        F4U av; av.u[0] = acc[r][0]; av.u[1] = acc[r][1];
        float4 xv = *(const float4*)(xs + (i0 + r) * 64 + j0);
        float4 tn;
        tn.x = 2.f * av.s[0] - xv.x;
        tn.y = 2.f * av.s[1] - xv.y;
        tn.z = 2.f * av.s[2] - xv.z;
        tn.w = 2.f * av.s[3] - xv.w;
        *(float4*)(xsT + (i0 + r) * 68 + j0) = tn;
    }
    __syncthreads();

    // out += Tn @ F2
    mm64p<68, 64>(xsT, fs, outa, i0, j0);

    // store g[(b*64+n)*32 + l][h]
#pragma unroll
    for (int r = 0; r < 4; r++) {
        F4U o; o.u[0] = outa[r][0]; o.u[1] = outa[r][1];
        size_t off = (((size_t)b * 64 + i0 + r) * 32 + l) * 64 + j0;
        *(float4*)(g_g + off) = o.f;
    }
}

// ---------------------------------------------------------------------------
// Kernel 2a: gi = g @ w_ih^T + b_ih.  grid=(8192,3), block=256.
// ---------------------------------------------------------------------------
__global__ void __launch_bounds__(256) k2a_gi(const float* __restrict__ w_ih,
                                              const float* __restrict__ b_ih) {
    __shared__ __align__(16) float As[4096];
    __shared__ __align__(16) float Bs[64 * 68];

    const int tid = threadIdx.x;
    const int rb = blockIdx.x;
    const int panel = blockIdx.y;

    const float* src = g_g + (size_t)rb * 4096;
#pragma unroll
    for (int k = 0; k < 4; k++) {
        int v = (tid + k * 256) << 2;
        *(float4*)(As + v) = *(const float4*)(src + v);
    }
    for (int i = tid; i < 4096; i += 256) {
        int row = i >> 6, f = i & 63;
        Bs[f * 68 + row] = w_ih[(panel * 64 + row) * 64 + f];
    }
    __syncthreads();

    const int tr = tid >> 4, tc = tid & 15;
    const int i0 = tr << 2, j0 = tc << 2;
    ull acc[4][2];
    zacc(acc);
    mm64p<64, 68>(As, Bs, acc, i0, j0);

    const float4 bi = *(const float4*)(b_ih + panel * 64 + j0);
#pragma unroll
    for (int r = 0; r < 4; r++) {
        F4U o; o.u[0] = acc[r][0]; o.u[1] = acc[r][1];
        size_t off = ((size_t)rb * 64 + i0 + r) * 192 + panel * 64 + j0;
        *(float4*)(g_gi + off) = make_float4(o.s[0] + bi.x, o.s[1] + bi.y,
                                             o.s[2] + bi.z, o.s[3] + bi.w);
    }
}

// ---------------------------------------------------------------------------
// Kernel 2b: GRU recurrence + fused FC dot.  grid=1024 (16 seqs each), block=192.
// ---------------------------------------------------------------------------
__global__ void __launch_bounds__(192) k2b_gru(const float* __restrict__ w_hh,
                                               const float* __restrict__ b_hh,
                                               const float* __restrict__ fc_w) {
    extern __shared__ __align__(16) float sm2[];
    float* wT    = sm2;             // 12544 (stride 196)
    float* gates = sm2 + 12544;     // 4096
    float* hs    = sm2 + 16640;     // 1024
    float* bhh   = sm2 + 17664;     // 192

    const int tid = threadIdx.x;
    const int seq0 = blockIdx.x * 16;
    const int n0 = seq0 & 63;

    for (int i = tid; i < 12288; i += 192) {
        int row = i >> 6, f = i & 63;
        wT[f * 196 + row] = w_hh[i];
    }
    bhh[tid] = b_hh[tid];
    for (int i = tid; i < 1024; i += 192) hs[i] = 0.f;
    __syncthreads();

    const int cg = tid % 48, sr = tid / 48;
    const int s0 = sr * 4, c0 = cg * 4;
    float fcacc = 0.f;

    for (int l = 0; l < 32; l++) {
        ull acc[4][2];
        zacc(acc);
        mm64p<64, 196>(hs, wT, acc, s0, c0);

        const float4 bh4 = *(const float4*)(bhh + c0);
#pragma unroll
        for (int s = 0; s < 4; s++) {
            const int sl = s0 + s;
            F4U av; av.u[0] = acc[s][0]; av.u[1] = acc[s][1];
            const float4 gi4 =
                *(const float4*)(g_gi + ((size_t)(seq0 + sl) * 32 + l) * 192 + c0);
            if (c0 < 128) {
                float4 o;
                o.x = av.s[0] + bh4.x + gi4.x;
                o.y = av.s[1] + bh4.y + gi4.y;
                o.z = av.s[2] + bh4.z + gi4.z;
                o.w = av.s[3] + bh4.w + gi4.w;
                *(float4*)(gates + sl * 256 + c0) = o;
            } else {
                float4 hn4;
                hn4.x = av.s[0] + bh4.x;
                hn4.y = av.s[1] + bh4.y;
                hn4.z = av.s[2] + bh4.z;
                hn4.w = av.s[3] + bh4.w;
                *(float4*)(gates + sl * 256 + c0 + 64) = hn4;   // h_n
                *(float4*)(gates + sl * 256 + c0) = gi4;        // i_n
            }
        }
        __syncthreads();

        for (int i = tid; i < 1024; i += 192) {
            int s = i >> 6, j = i & 63;
            const float* gp = gates + s * 256 + j;
            float rg = 1.f / (1.f + expf(-gp[0]));
            float zg = 1.f / (1.f + expf(-gp[64]));
            float ng = tanhf(gp[128] + rg * gp[192]);
            float h = hs[s * 64 + j];
            float hn = (1.f - zg) * ng + zg * h;
            hs[s * 64 + j] = hn;
            fcacc += hn * fc_w[(n0 + s) * 2048 + l * 64 + j];
        }
        __syncthreads();
    }

#pragma unroll
    for (int o = 16; o > 0; o >>= 1)
        fcacc += __shfl_down_sync(0xffffffffu, fcacc, o);
    float* red = gates;
    if ((tid & 31) == 0) red[tid >> 5] = fcacc;
    __syncthreads();
    if (tid == 0) {
        float s = 0.f;
#pragma unroll
        for (int w = 0; w < 6; w++) s += red[w];
        g_part[blockIdx.x] = s;
    }
}

// ---------------------------------------------------------------------------
__global__ void k3_fc(const float* __restrict__ fc_b, float* __restrict__ out) {
    int b = threadIdx.x;
    float s = fc_b[0];
#pragma unroll
    for (int k = 0; k < 4; k++) s += g_part[b * 4 + k];
    out[b] = s;
}

// ---------------------------------------------------------------------------
extern "C" void kernel_launch(void* const* d_in, const int* in_sizes, int n_in,
                              void* d_out, int out_size) {
    const float* x    = (const float*)d_in[0];
    const float* filt = (const float*)d_in[1];
    const float* w_ih = (const float*)d_in[2];
    const float* w_hh = (const float*)d_in[3];
    const float* b_ih = (const float*)d_in[4];
    const float* b_hh = (const float*)d_in[5];
    const float* fc_w = (const float*)d_in[6];
    const float* fc_b = (const float*)d_in[7];
    float* out = (float*)d_out;

    const int SMEM1 = 24896 * 4;
    const int SMEM2 = 17856 * 4;
    cudaFuncSetAttribute(k1_cheb, cudaFuncAttributeMaxDynamicSharedMemorySize, SMEM1);
    cudaFuncSetAttribute(k2b_gru, cudaFuncAttributeMaxDynamicSharedMemorySize, SMEM2);

    k1_cheb<<<8192, 256, SMEM1>>>(x, filt);
    k2a_gi<<<dim3(8192, 3), 256>>>(w_ih, b_ih);
    k2b_gru<<<1024, 192, SMEM2>>>(w_hh, b_hh, fc_w);
    k3_fc<<<1, 256>>>(fc_b, out);
}

// round 4
// speedup vs baseline: 1.2050x; 1.1924x over previous
#include <cuda_runtime.h>
#include <math.h>
#include <stdint.h>

// ---------------------------------------------------------------------------
// STGNN R4:
//  k0_prepG : Gcat[192][192] = stack_k(F_k @ w_ih^T)
//  k1_cheb  : Gram(fp32) + exp + top8 -> sparse Cheb -> A=[Tx0|Tx1|Tx2] rows
//  k2_gemm  : gi = A @ Gcat + b_ih via mma.sync tf32 (legacy tensor path)
//  k2b_gru  : fp32 GRU recurrence + fused FC dot
//  k3_fc    : final reduce
// ---------------------------------------------------------------------------

#define DEV static __device__ __forceinline__
typedef unsigned long long ull;

// device scratch (no allocations allowed)
__device__ float g_t[524288ull * 192];   // A rows: [m*64+n][192]  (384MB)
__device__ float g_gi[524288ull * 192];  // gi: [(b*64+n)*32+l][192] (384MB)
__device__ float g_G[192 * 192];         // Gcat
__device__ float g_part[1024];           // per-block FC partials

DEV uint32_t to_tf32(float f) {
    uint32_t r;
    asm("cvt.rna.tf32.f32 %0, %1;" : "=r"(r) : "f"(f));
    return r;
}

DEV void mma8(float* c, const uint32_t* a, const uint32_t* b) {
    asm volatile(
        "mma.sync.aligned.m16n8k8.row.col.f32.tf32.tf32.f32 "
        "{%0,%1,%2,%3}, {%4,%5,%6,%7}, {%8,%9}, {%0,%1,%2,%3};"
        : "+f"(c[0]), "+f"(c[1]), "+f"(c[2]), "+f"(c[3])
        : "r"(a[0]), "r"(a[1]), "r"(a[2]), "r"(a[3]), "r"(b[0]), "r"(b[1]));
}

// ---------------- scalar FFMA2 GEMM helper (Gram, GRU) ----------------
union F4U { float4 f; ull u[2]; float s[4]; };
DEV ull pack2(float a) {
    ull r;
    asm("mov.b64 %0, {%1, %1};" : "=l"(r) : "r"(__float_as_uint(a)));
    return r;
}
DEV void fma2(ull& acc, ull a, ull b) {
    asm("fma.rn.f32x2 %0, %1, %2, %0;" : "+l"(acc) : "l"(a), "l"(b));
}
template <int LDA, int LDB>
DEV void mm64p(const float* A, const float* B, ull (&acc)[4][2], int i0, int j0) {
#pragma unroll 4
    for (int f = 0; f < 64; f += 4) {
        F4U a[4], bb[4];
#pragma unroll
        for (int r = 0; r < 4; r++)
            a[r].f = *(const float4*)(A + (i0 + r) * LDA + f);
#pragma unroll
        for (int k = 0; k < 4; k++)
            bb[k].f = *(const float4*)(B + (f + k) * LDB + j0);
#pragma unroll
        for (int k = 0; k < 4; k++) {
#pragma unroll
            for (int r = 0; r < 4; r++) {
                ull ad = pack2(a[r].s[k]);
                fma2(acc[r][0], ad, bb[k].u[0]);
                fma2(acc[r][1], ad, bb[k].u[1]);
            }
        }
    }
}
DEV void zacc(ull (&a)[4][2]) {
#pragma unroll
    for (int r = 0; r < 4; r++) { a[r][0] = 0ull; a[r][1] = 0ull; }
}

// ---------------------------------------------------------------------------
// k0: Gcat[(k*64+f)][j] = sum_h F[k][f][h] * w_ih[j][h].  grid=3, block=192.
// ---------------------------------------------------------------------------
__global__ void __launch_bounds__(192) k0_prepG(const float* __restrict__ filters,
                                                const float* __restrict__ w_ih) {
    __shared__ float Fs[4096];
    const int k = blockIdx.x, j = threadIdx.x;
    for (int i = j; i < 4096; i += 192) Fs[i] = filters[k * 4096 + i];
    float w[64];
#pragma unroll
    for (int h = 0; h < 64; h++) w[h] = w_ih[j * 64 + h];
    __syncthreads();
    for (int f = 0; f < 64; f++) {
        float s = 0.f;
#pragma unroll
        for (int h = 0; h < 64; h++) s = fmaf(Fs[f * 64 + h], w[h], s);
        g_G[(k * 64 + f) * 192 + j] = s;
    }
}

// ---------------------------------------------------------------------------
// k1: per-m: Gram(fp32) -> sim -> top8 -> sparse Tx1/Tx2 -> write A rows.
// grid=8192, block=256, smem 70912 B.
// ---------------------------------------------------------------------------
__global__ void __launch_bounds__(256) k1_cheb(const float* __restrict__ x) {
    extern __shared__ __align__(16) float sm1[];
    float* xs  = sm1;                 // 4096
    float* xsT = sm1 + 4096;          // 4352 (stride 68)
    float* adj = sm1 + 8448;          // 4096 (Gram -> sim)
    float* t1  = sm1 + 12544;         // 4096 (Tx1)
    float* sq  = sm1 + 16640;         // 64
    float* val = sm1 + 16704;         // 512
    int*   idx = (int*)(sm1 + 17216); // 512

    const int m = blockIdx.x;
    const int b = m >> 5, l = m & 31;
    const int tid = threadIdx.x;

    const float* xb = x + (size_t)b * 64 * 2048 + l * 64;
#pragma unroll
    for (int k = 0; k < 4; k++) {
        int v = tid + k * 256;
        int n = v >> 4, fo = (v & 15) << 2;
        *(float4*)(xs + n * 64 + fo) = *(const float4*)(xb + (size_t)n * 2048 + fo);
    }
    __syncthreads();

    for (int i = tid; i < 4096; i += 256) {
        int n = i >> 6, f = i & 63;
        xsT[f * 68 + n] = xs[i];
    }
    __syncthreads();

    const int tr = tid >> 4, tc = tid & 15;
    const int i0 = tr << 2, j0 = tc << 2;

    // Gram = xs @ xs^T (fp32)
    ull acc[4][2];
    zacc(acc);
    mm64p<64, 68>(xs, xsT, acc, i0, j0);
#pragma unroll
    for (int r = 0; r < 4; r++) {
        F4U o; o.u[0] = acc[r][0]; o.u[1] = acc[r][1];
        *(float4*)(adj + (i0 + r) * 64 + j0) = o.f;
    }
    __syncthreads();

    if (tid < 64) sq[tid] = adj[tid * 64 + tid];
    __syncthreads();

    for (int i = tid; i < 4096; i += 256) {
        int r = i >> 6, c = i & 63;
        float d2 = sq[r] + sq[c] - 2.f * adj[i];
        adj[i] = expf(-fmaxf(d2, 0.f));
    }
    __syncthreads();

    // top-8 per row -> (val, idx), ascending j, jax tie-break (earliest)
    if (tid < 64) {
        float* row = adj + tid * 64;
        float tk[8];
#pragma unroll
        for (int i = 0; i < 8; i++) tk[i] = -1.f;
        for (int j = 0; j < 64; j++) {
            float v = row[j];
#pragma unroll
            for (int i = 0; i < 8; i++) {
                float mx = fmaxf(tk[i], v);
                v = fminf(tk[i], v);
                tk[i] = mx;
            }
        }
        float thr = tk[7];
        int cg = 0;
        for (int j = 0; j < 64; j++) cg += (row[j] > thr) ? 1 : 0;
        int rem = 8 - cg;
        int c = 0;
        for (int j = 0; j < 64; j++) {
            float v = row[j];
            bool take = false;
            if (v > thr) take = true;
            else if (v == thr && rem > 0) { take = true; rem--; }
            if (take) { val[tid * 8 + c] = v; idx[tid * 8 + c] = j; c++; }
        }
    }
    __syncthreads();

    // sparse Cheb: 4 threads per row, 16 f-cols each
    const int row = tid >> 2, f0 = (tid & 3) << 4;
    float lv[8];
    int lj[8];
#pragma unroll
    for (int i = 0; i < 8; i++) { lv[i] = val[row * 8 + i]; lj[i] = idx[row * 8 + i]; }

    float4 a4[4];
#pragma unroll
    for (int q = 0; q < 4; q++) a4[q] = make_float4(0.f, 0.f, 0.f, 0.f);
#pragma unroll
    for (int i = 0; i < 8; i++) {
        float v = lv[i];
        const float4* xr = (const float4*)(xs + lj[i] * 64 + f0);
#pragma unroll
        for (int q = 0; q < 4; q++) {
            float4 t = xr[q];
            a4[q].x = fmaf(v, t.x, a4[q].x);
            a4[q].y = fmaf(v, t.y, a4[q].y);
            a4[q].z = fmaf(v, t.z, a4[q].z);
            a4[q].w = fmaf(v, t.w, a4[q].w);
        }
    }
#pragma unroll
    for (int q = 0; q < 4; q++) *(float4*)(t1 + row * 64 + f0 + q * 4) = a4[q];
    __syncthreads();

    // Tx2 = 2*adj_sparse @ Tx1 - xs
    float4 b4[4];
#pragma unroll
    for (int q = 0; q < 4; q++) b4[q] = make_float4(0.f, 0.f, 0.f, 0.f);
#pragma unroll
    for (int i = 0; i < 8; i++) {
        float v = lv[i];
        const float4* tr4 = (const float4*)(t1 + lj[i] * 64 + f0);
#pragma unroll
        for (int q = 0; q < 4; q++) {
            float4 t = tr4[q];
            b4[q].x = fmaf(v, t.x, b4[q].x);
            b4[q].y = fmaf(v, t.y, b4[q].y);
            b4[q].z = fmaf(v, t.z, b4[q].z);
            b4[q].w = fmaf(v, t.w, b4[q].w);
        }
    }

    // write A row: [xs | Tx1 | Tx2]
    float* dst = g_t + ((size_t)m * 64 + row) * 192;
#pragma unroll
    for (int q = 0; q < 4; q++) {
        float4 xv = *(const float4*)(xs + row * 64 + f0 + q * 4);
        *(float4*)(dst + f0 + q * 4) = xv;
        *(float4*)(dst + 64 + f0 + q * 4) = a4[q];
        float4 tn;
        tn.x = 2.f * b4[q].x - xv.x;
        tn.y = 2.f * b4[q].y - xv.y;
        tn.z = 2.f * b4[q].z - xv.z;
        tn.w = 2.f * b4[q].w - xv.w;
        *(float4*)(dst + 128 + f0 + q * 4) = tn;
    }
}

// ---------------------------------------------------------------------------
// k2: gi = A @ Gcat + b_ih via tf32 mma.sync. grid=4096, block=256 (8 warps).
// CTA tile 128x192, K chunks of 32 (6 chunks), reg-staged double buffer.
// warp grid 2(M) x 4(N): warp tile 64x48 = 4 m16 x 6 n8.
// smem floats: A2 2x(128x36)=9216, B2 2x(32x200)=12800, bias 192 -> 88832 B.
// ---------------------------------------------------------------------------
#define LDA_S 36
#define LDB_S 200
#define SMEMG (22208 * 4)

__global__ void __launch_bounds__(256) k2_gemm(const float* __restrict__ b_ih) {
    extern __shared__ __align__(16) float smg[];
    float* A0   = smg;            // 9216
    float* B0   = smg + 9216;     // 12800
    float* bias = smg + 22016;    // 192

    const int tid = threadIdx.x;
    const int wid = tid >> 5, lid = tid & 31;
    const int g = lid >> 2, tg = lid & 3;
    const int wm = wid & 1, wn = wid >> 1;

    const size_t row0 = (size_t)blockIdx.x * 128;

    for (int i = tid; i < 192; i += 256) bias[i] = b_ih[i];

    float4 aR[4];
    float bR[24];
    auto ldg = [&](int c) {
#pragma unroll
        for (int t = 0; t < 4; t++) {
            int v = tid + (t << 8);
            int r = v >> 3, c4 = v & 7;
            aR[t] = *(const float4*)(g_t + (row0 + r) * 192 + c * 32 + c4 * 4);
        }
#pragma unroll
        for (int t = 0; t < 24; t++) {
            int e = tid + (t << 8);
            int kk = e / 192, n = e - kk * 192;
            bR[t] = g_G[(c * 32 + kk) * 192 + n];
        }
    };
    auto sts = [&](int buf) {
        uint32_t* ab = (uint32_t*)(A0 + buf * 4608);
        uint32_t* bb = (uint32_t*)(B0 + buf * 6400);
#pragma unroll
        for (int t = 0; t < 4; t++) {
            int v = tid + (t << 8);
            int r = v >> 3, c4 = v & 7;
            uint4 o;
            o.x = to_tf32(aR[t].x); o.y = to_tf32(aR[t].y);
            o.z = to_tf32(aR[t].z); o.w = to_tf32(aR[t].w);
            *(uint4*)(ab + r * LDA_S + c4 * 4) = o;
        }
#pragma unroll
        for (int t = 0; t < 24; t++) {
            int e = tid + (t << 8);
            int kk = e / 192, n = e - kk * 192;
            bb[kk * LDB_S + n] = to_tf32(bR[t]);
        }
    };

    float acc[4][6][4];
#pragma unroll
    for (int mt = 0; mt < 4; mt++)
#pragma unroll
        for (int nt = 0; nt < 6; nt++)
#pragma unroll
            for (int q = 0; q < 4; q++) acc[mt][nt][q] = 0.f;

    ldg(0);
    sts(0);
    __syncthreads();

    for (int c = 0; c < 6; c++) {
        if (c < 5) ldg(c + 1);
        const uint32_t* As = (const uint32_t*)(A0 + (c & 1) * 4608);
        const uint32_t* Bs = (const uint32_t*)(B0 + (c & 1) * 6400);
#pragma unroll
        for (int ks = 0; ks < 4; ks++) {
            const int kb = ks * 8;
            uint32_t af[4][4], bf[6][2];
#pragma unroll
            for (int mt = 0; mt < 4; mt++) {
                int mr = wm * 64 + mt * 16 + g;
                af[mt][0] = As[mr * LDA_S + kb + tg];
                af[mt][1] = As[(mr + 8) * LDA_S + kb + tg];
                af[mt][2] = As[mr * LDA_S + kb + tg + 4];
                af[mt][3] = As[(mr + 8) * LDA_S + kb + tg + 4];
            }
#pragma unroll
            for (int nt = 0; nt < 6; nt++) {
                int nc = wn * 48 + nt * 8 + g;
                bf[nt][0] = Bs[(kb + tg) * LDB_S + nc];
                bf[nt][1] = Bs[(kb + tg + 4) * LDB_S + nc];
            }
#pragma unroll
            for (int mt = 0; mt < 4; mt++)
#pragma unroll
                for (int nt = 0; nt < 6; nt++)
                    mma8(acc[mt][nt], af[mt], bf[nt]);
        }
        __syncthreads();
        if (c < 5) {
            sts((c + 1) & 1);
            __syncthreads();
        }
    }

    // epilogue: add bias, permuted store to g_gi
#pragma unroll
    for (int mt = 0; mt < 4; mt++) {
#pragma unroll
        for (int half = 0; half < 2; half++) {
            size_t gr = row0 + wm * 64 + mt * 16 + g + half * 8;
            int mm = (int)(gr >> 6), n = (int)(gr & 63);
            float* orow = g_gi + (((size_t)(mm >> 5) * 64 + n) * 32 + (mm & 31)) * 192;
#pragma unroll
            for (int nt = 0; nt < 6; nt++) {
                int nc = wn * 48 + nt * 8 + tg * 2;
                float2 o;
                o.x = acc[mt][nt][half * 2 + 0] + bias[nc];
                o.y = acc[mt][nt][half * 2 + 1] + bias[nc + 1];
                *(float2*)(orow + nc) = o;
            }
        }
    }
}

// ---------------------------------------------------------------------------
// k2b: GRU recurrence + fused FC dot. grid=1024 (16 seqs), block=192.
// ---------------------------------------------------------------------------
__global__ void __launch_bounds__(192) k2b_gru(const float* __restrict__ w_hh,
                                               const float* __restrict__ b_hh,
                                               const float* __restrict__ fc_w) {
    extern __shared__ __align__(16) float sm2[];
    float* wT    = sm2;             // 12544 (stride 196)
    float* gates = sm2 + 12544;     // 4096
    float* hs    = sm2 + 16640;     // 1024
    float* bhh   = sm2 + 17664;     // 192

    const int tid = threadIdx.x;
    const int seq0 = blockIdx.x * 16;
    const int n0 = seq0 & 63;

    for (int i = tid; i < 12288; i += 192) {
        int row = i >> 6, f = i & 63;
        wT[f * 196 + row] = w_hh[i];
    }
    bhh[tid] = b_hh[tid];
    for (int i = tid; i < 1024; i += 192) hs[i] = 0.f;
    __syncthreads();

    const int cg = tid % 48, sr = tid / 48;
    const int s0 = sr * 4, c0 = cg * 4;
    float fcacc = 0.f;

    for (int l = 0; l < 32; l++) {
        ull acc[4][2];
        zacc(acc);
        mm64p<64, 196>(hs, wT, acc, s0, c0);

        const float4 bh4 = *(const float4*)(bhh + c0);
#pragma unroll
        for (int s = 0; s < 4; s++) {
            const int sl = s0 + s;
            F4U av; av.u[0] = acc[s][0]; av.u[1] = acc[s][1];
            const float4 gi4 =
                *(const float4*)(g_gi + ((size_t)(seq0 + sl) * 32 + l) * 192 + c0);
            if (c0 < 128) {
                float4 o;
                o.x = av.s[0] + bh4.x + gi4.x;
                o.y = av.s[1] + bh4.y + gi4.y;
                o.z = av.s[2] + bh4.z + gi4.z;
                o.w = av.s[3] + bh4.w + gi4.w;
                *(float4*)(gates + sl * 256 + c0) = o;
            } else {
                float4 hn4;
                hn4.x = av.s[0] + bh4.x;
                hn4.y = av.s[1] + bh4.y;
                hn4.z = av.s[2] + bh4.z;
                hn4.w = av.s[3] + bh4.w;
                *(float4*)(gates + sl * 256 + c0 + 64) = hn4;   // h_n
                *(float4*)(gates + sl * 256 + c0) = gi4;        // i_n
            }
        }
        __syncthreads();

        for (int i = tid; i < 1024; i += 192) {
            int s = i >> 6, j = i & 63;
            const float* gp = gates + s * 256 + j;
            float rg = 1.f / (1.f + expf(-gp[0]));
            float zg = 1.f / (1.f + expf(-gp[64]));
            float ng = tanhf(gp[128] + rg * gp[192]);
            float h = hs[s * 64 + j];
            float hn = (1.f - zg) * ng + zg * h;
            hs[s * 64 + j] = hn;
            fcacc += hn * fc_w[(n0 + s) * 2048 + l * 64 + j];
        }
        __syncthreads();
    }

#pragma unroll
    for (int o = 16; o > 0; o >>= 1)
        fcacc += __shfl_down_sync(0xffffffffu, fcacc, o);
    float* red = gates;
    if ((tid & 31) == 0) red[tid >> 5] = fcacc;
    __syncthreads();
    if (tid == 0) {
        float s = 0.f;
#pragma unroll
        for (int w = 0; w < 6; w++) s += red[w];
        g_part[blockIdx.x] = s;
    }
}

// ---------------------------------------------------------------------------
__global__ void k3_fc(const float* __restrict__ fc_b, float* __restrict__ out) {
    int b = threadIdx.x;
    float s = fc_b[0];
#pragma unroll
    for (int k = 0; k < 4; k++) s += g_part[b * 4 + k];
    out[b] = s;
}

// ---------------------------------------------------------------------------
extern "C" void kernel_launch(void* const* d_in, const int* in_sizes, int n_in,
                              void* d_out, int out_size) {
    const float* x    = (const float*)d_in[0];
    const float* filt = (const float*)d_in[1];
    const float* w_ih = (const float*)d_in[2];
    const float* w_hh = (const float*)d_in[3];
    const float* b_ih = (const float*)d_in[4];
    const float* b_hh = (const float*)d_in[5];
    const float* fc_w = (const float*)d_in[6];
    const float* fc_b = (const float*)d_in[7];
    float* out = (float*)d_out;

    const int SMEM1 = 17728 * 4;   // 70912 B
    const int SMEM2 = 17856 * 4;   // 71424 B
    cudaFuncSetAttribute(k1_cheb, cudaFuncAttributeMaxDynamicSharedMemorySize, SMEM1);
    cudaFuncSetAttribute(k2_gemm, cudaFuncAttributeMaxDynamicSharedMemorySize, SMEMG);
    cudaFuncSetAttribute(k2b_gru, cudaFuncAttributeMaxDynamicSharedMemorySize, SMEM2);

    k0_prepG<<<3, 192>>>(filt, w_ih);
    k1_cheb<<<8192, 256, SMEM1>>>(x);
    k2_gemm<<<4096, 256, SMEMG>>>(b_ih);
    k2b_gru<<<1024, 192, SMEM2>>>(w_hh, b_hh, fc_w);
    k3_fc<<<1, 256>>>(fc_b, out);
}

// round 5
// speedup vs baseline: 1.5930x; 1.3219x over previous
#include <cuda_runtime.h>
#include <math.h>
#include <stdint.h>

// ---------------------------------------------------------------------------
// STGNN R5:
//  k0_prepG : Gcat[192][192] = stack_k(F_k @ w_ih^T)
//  k1_cheb  : Gram(fp32) + exp + top8 -> sparse Cheb -> A=[Tx0|Tx1|Tx2] rows
//  k2_gemm  : gi = A @ Gcat + bias via mma.sync tf32, epilogue stores FRAGMENT
//             layout gi2[seqtile][l][ntile][lane]{4}; bias folds b_hh for r,z
//  k2b_gru  : tensor-core GRU: per-warp 16 seqs, gates in registers, fused FC
//  k3_fc    : final reduce
// ---------------------------------------------------------------------------

#define DEV static __device__ __forceinline__
typedef unsigned long long ull;

// device scratch (no allocations allowed)
__device__ float g_t[524288ull * 192];   // A rows: [m*64+n][192]
__device__ float g_gi[524288ull * 192];  // gi2 fragments: [(st*32+l)*24+nt][lane][4]
__device__ float g_G[192 * 192];         // Gcat
__device__ float g_part[1024];           // per-warp FC partials

DEV uint32_t to_tf32(float f) {
    uint32_t r;
    asm("cvt.rna.tf32.f32 %0, %1;" : "=r"(r) : "f"(f));
    return r;
}

DEV void mma8(float* c, const uint32_t* a, const uint32_t* b) {
    asm volatile(
        "mma.sync.aligned.m16n8k8.row.col.f32.tf32.tf32.f32 "
        "{%0,%1,%2,%3}, {%4,%5,%6,%7}, {%8,%9}, {%0,%1,%2,%3};"
        : "+f"(c[0]), "+f"(c[1]), "+f"(c[2]), "+f"(c[3])
        : "r"(a[0]), "r"(a[1]), "r"(a[2]), "r"(a[3]), "r"(b[0]), "r"(b[1]));
}

// ---------------- scalar FFMA2 GEMM helper (Gram) ----------------
union F4U { float4 f; ull u[2]; float s[4]; };
DEV ull pack2(float a) {
    ull r;
    asm("mov.b64 %0, {%1, %1};" : "=l"(r) : "r"(__float_as_uint(a)));
    return r;
}
DEV void fma2(ull& acc, ull a, ull b) {
    asm("fma.rn.f32x2 %0, %1, %2, %0;" : "+l"(acc) : "l"(a), "l"(b));
}
template <int LDA, int LDB>
DEV void mm64p(const float* A, const float* B, ull (&acc)[4][2], int i0, int j0) {
#pragma unroll 4
    for (int f = 0; f < 64; f += 4) {
        F4U a[4], bb[4];
#pragma unroll
        for (int r = 0; r < 4; r++)
            a[r].f = *(const float4*)(A + (i0 + r) * LDA + f);
#pragma unroll
        for (int k = 0; k < 4; k++)
            bb[k].f = *(const float4*)(B + (f + k) * LDB + j0);
#pragma unroll
        for (int k = 0; k < 4; k++) {
#pragma unroll
            for (int r = 0; r < 4; r++) {
                ull ad = pack2(a[r].s[k]);
                fma2(acc[r][0], ad, bb[k].u[0]);
                fma2(acc[r][1], ad, bb[k].u[1]);
            }
        }
    }
}
DEV void zacc(ull (&a)[4][2]) {
#pragma unroll
    for (int r = 0; r < 4; r++) { a[r][0] = 0ull; a[r][1] = 0ull; }
}

// ---------------------------------------------------------------------------
// k0: Gcat[(k*64+f)][j] = sum_h F[k][f][h] * w_ih[j][h].  grid=3, block=192.
// ---------------------------------------------------------------------------
__global__ void __launch_bounds__(192) k0_prepG(const float* __restrict__ filters,
                                                const float* __restrict__ w_ih) {
    __shared__ float Fs[4096];
    const int k = blockIdx.x, j = threadIdx.x;
    for (int i = j; i < 4096; i += 192) Fs[i] = filters[k * 4096 + i];
    float w[64];
#pragma unroll
    for (int h = 0; h < 64; h++) w[h] = w_ih[j * 64 + h];
    __syncthreads();
    for (int f = 0; f < 64; f++) {
        float s = 0.f;
#pragma unroll
        for (int h = 0; h < 64; h++) s = fmaf(Fs[f * 64 + h], w[h], s);
        g_G[(k * 64 + f) * 192 + j] = s;
    }
}

// ---------------------------------------------------------------------------
// k1: per-m: Gram(fp32) -> sim -> top8 -> sparse Tx1/Tx2 -> write A rows.
// grid=8192, block=256, smem 70912 B.
// ---------------------------------------------------------------------------
__global__ void __launch_bounds__(256) k1_cheb(const float* __restrict__ x) {
    extern __shared__ __align__(16) float sm1[];
    float* xs  = sm1;                 // 4096
    float* xsT = sm1 + 4096;          // 4352 (stride 68)
    float* adj = sm1 + 8448;          // 4096 (Gram -> sim)
    float* t1  = sm1 + 12544;         // 4096 (Tx1)
    float* sq  = sm1 + 16640;         // 64
    float* val = sm1 + 16704;         // 512
    int*   idx = (int*)(sm1 + 17216); // 512

    const int m = blockIdx.x;
    const int b = m >> 5, l = m & 31;
    const int tid = threadIdx.x;

    const float* xb = x + (size_t)b * 64 * 2048 + l * 64;
#pragma unroll
    for (int k = 0; k < 4; k++) {
        int v = tid + k * 256;
        int n = v >> 4, fo = (v & 15) << 2;
        *(float4*)(xs + n * 64 + fo) = *(const float4*)(xb + (size_t)n * 2048 + fo);
    }
    __syncthreads();

    for (int i = tid; i < 4096; i += 256) {
        int n = i >> 6, f = i & 63;
        xsT[f * 68 + n] = xs[i];
    }
    __syncthreads();

    const int tr = tid >> 4, tc = tid & 15;
    const int i0 = tr << 2, j0 = tc << 2;

    ull acc[4][2];
    zacc(acc);
    mm64p<64, 68>(xs, xsT, acc, i0, j0);
#pragma unroll
    for (int r = 0; r < 4; r++) {
        F4U o; o.u[0] = acc[r][0]; o.u[1] = acc[r][1];
        *(float4*)(adj + (i0 + r) * 64 + j0) = o.f;
    }
    __syncthreads();

    if (tid < 64) sq[tid] = adj[tid * 64 + tid];
    __syncthreads();

    for (int i = tid; i < 4096; i += 256) {
        int r = i >> 6, c = i & 63;
        float d2 = sq[r] + sq[c] - 2.f * adj[i];
        adj[i] = expf(-fmaxf(d2, 0.f));
    }
    __syncthreads();

    if (tid < 64) {
        float* row = adj + tid * 64;
        float tk[8];
#pragma unroll
        for (int i = 0; i < 8; i++) tk[i] = -1.f;
        for (int j = 0; j < 64; j++) {
            float v = row[j];
#pragma unroll
            for (int i = 0; i < 8; i++) {
                float mx = fmaxf(tk[i], v);
                v = fminf(tk[i], v);
                tk[i] = mx;
            }
        }
        float thr = tk[7];
        int cg = 0;
        for (int j = 0; j < 64; j++) cg += (row[j] > thr) ? 1 : 0;
        int rem = 8 - cg;
        int c = 0;
        for (int j = 0; j < 64; j++) {
            float v = row[j];
            bool take = false;
            if (v > thr) take = true;
            else if (v == thr && rem > 0) { take = true; rem--; }
            if (take) { val[tid * 8 + c] = v; idx[tid * 8 + c] = j; c++; }
        }
    }
    __syncthreads();

    const int row = tid >> 2, f0 = (tid & 3) << 4;
    float lv[8];
    int lj[8];
#pragma unroll
    for (int i = 0; i < 8; i++) { lv[i] = val[row * 8 + i]; lj[i] = idx[row * 8 + i]; }

    float4 a4[4];
#pragma unroll
    for (int q = 0; q < 4; q++) a4[q] = make_float4(0.f, 0.f, 0.f, 0.f);
#pragma unroll
    for (int i = 0; i < 8; i++) {
        float v = lv[i];
        const float4* xr = (const float4*)(xs + lj[i] * 64 + f0);
#pragma unroll
        for (int q = 0; q < 4; q++) {
            float4 t = xr[q];
            a4[q].x = fmaf(v, t.x, a4[q].x);
            a4[q].y = fmaf(v, t.y, a4[q].y);
            a4[q].z = fmaf(v, t.z, a4[q].z);
            a4[q].w = fmaf(v, t.w, a4[q].w);
        }
    }
#pragma unroll
    for (int q = 0; q < 4; q++) *(float4*)(t1 + row * 64 + f0 + q * 4) = a4[q];
    __syncthreads();

    float4 b4[4];
#pragma unroll
    for (int q = 0; q < 4; q++) b4[q] = make_float4(0.f, 0.f, 0.f, 0.f);
#pragma unroll
    for (int i = 0; i < 8; i++) {
        float v = lv[i];
        const float4* tr4 = (const float4*)(t1 + lj[i] * 64 + f0);
#pragma unroll
        for (int q = 0; q < 4; q++) {
            float4 t = tr4[q];
            b4[q].x = fmaf(v, t.x, b4[q].x);
            b4[q].y = fmaf(v, t.y, b4[q].y);
            b4[q].z = fmaf(v, t.z, b4[q].z);
            b4[q].w = fmaf(v, t.w, b4[q].w);
        }
    }

    float* dst = g_t + ((size_t)m * 64 + row) * 192;
#pragma unroll
    for (int q = 0; q < 4; q++) {
        float4 xv = *(const float4*)(xs + row * 64 + f0 + q * 4);
        *(float4*)(dst + f0 + q * 4) = xv;
        *(float4*)(dst + 64 + f0 + q * 4) = a4[q];
        float4 tn;
        tn.x = 2.f * b4[q].x - xv.x;
        tn.y = 2.f * b4[q].y - xv.y;
        tn.z = 2.f * b4[q].z - xv.z;
        tn.w = 2.f * b4[q].w - xv.w;
        *(float4*)(dst + 128 + f0 + q * 4) = tn;
    }
}

// ---------------------------------------------------------------------------
// k2: gi = A @ Gcat + bias via tf32 mma.sync. grid=4096, block=256 (8 warps).
// bias = b_ih + b_hh for cols<128 (r,z folded); epilogue: fragment layout.
// ---------------------------------------------------------------------------
#define LDA_S 36
#define LDB_S 200
#define SMEMG (22208 * 4)

__global__ void __launch_bounds__(256) k2_gemm(const float* __restrict__ b_ih,
                                               const float* __restrict__ b_hh) {
    extern __shared__ __align__(16) float smg[];
    float* A0   = smg;            // 9216
    float* B0   = smg + 9216;     // 12800
    float* bias = smg + 22016;    // 192

    const int tid = threadIdx.x;
    const int wid = tid >> 5, lid = tid & 31;
    const int g = lid >> 2, tg = lid & 3;
    const int wm = wid & 1, wn = wid >> 1;

    const size_t row0 = (size_t)blockIdx.x * 128;

    for (int i = tid; i < 192; i += 256)
        bias[i] = b_ih[i] + (i < 128 ? b_hh[i] : 0.f);

    float4 aR[4];
    float bR[24];
    auto ldg = [&](int c) {
#pragma unroll
        for (int t = 0; t < 4; t++) {
            int v = tid + (t << 8);
            int r = v >> 3, c4 = v & 7;
            aR[t] = *(const float4*)(g_t + (row0 + r) * 192 + c * 32 + c4 * 4);
        }
#pragma unroll
        for (int t = 0; t < 24; t++) {
            int e = tid + (t << 8);
            int kk = e / 192, n = e - kk * 192;
            bR[t] = g_G[(c * 32 + kk) * 192 + n];
        }
    };
    auto sts = [&](int buf) {
        uint32_t* ab = (uint32_t*)(A0 + buf * 4608);
        uint32_t* bb = (uint32_t*)(B0 + buf * 6400);
#pragma unroll
        for (int t = 0; t < 4; t++) {
            int v = tid + (t << 8);
            int r = v >> 3, c4 = v & 7;
            uint4 o;
            o.x = to_tf32(aR[t].x); o.y = to_tf32(aR[t].y);
            o.z = to_tf32(aR[t].z); o.w = to_tf32(aR[t].w);
            *(uint4*)(ab + r * LDA_S + c4 * 4) = o;
        }
#pragma unroll
        for (int t = 0; t < 24; t++) {
            int e = tid + (t << 8);
            int kk = e / 192, n = e - kk * 192;
            bb[kk * LDB_S + n] = to_tf32(bR[t]);
        }
    };

    float acc[4][6][4];
#pragma unroll
    for (int mt = 0; mt < 4; mt++)
#pragma unroll
        for (int nt = 0; nt < 6; nt++)
#pragma unroll
            for (int q = 0; q < 4; q++) acc[mt][nt][q] = 0.f;

    ldg(0);
    sts(0);
    __syncthreads();

    for (int c = 0; c < 6; c++) {
        if (c < 5) ldg(c + 1);
        const uint32_t* As = (const uint32_t*)(A0 + (c & 1) * 4608);
        const uint32_t* Bs = (const uint32_t*)(B0 + (c & 1) * 6400);
#pragma unroll
        for (int ks = 0; ks < 4; ks++) {
            const int kb = ks * 8;
            uint32_t af[4][4], bf[6][2];
#pragma unroll
            for (int mt = 0; mt < 4; mt++) {
                int mr = wm * 64 + mt * 16 + g;
                af[mt][0] = As[mr * LDA_S + kb + tg];
                af[mt][1] = As[(mr + 8) * LDA_S + kb + tg];
                af[mt][2] = As[mr * LDA_S + kb + tg + 4];
                af[mt][3] = As[(mr + 8) * LDA_S + kb + tg + 4];
            }
#pragma unroll
            for (int nt = 0; nt < 6; nt++) {
                int nc = wn * 48 + nt * 8 + g;
                bf[nt][0] = Bs[(kb + tg) * LDB_S + nc];
                bf[nt][1] = Bs[(kb + tg + 4) * LDB_S + nc];
            }
#pragma unroll
            for (int mt = 0; mt < 4; mt++)
#pragma unroll
                for (int nt = 0; nt < 6; nt++)
                    mma8(acc[mt][nt], af[mt], bf[nt]);
        }
        __syncthreads();
        if (c < 5) {
            sts((c + 1) & 1);
            __syncthreads();
        }
    }

    // epilogue: add bias, store FRAGMENT layout: gi2[((st*32+l)*24+nt)*32+lid]
    const size_t m_glob = (size_t)blockIdx.x * 2 + wm;
    const int bb2 = (int)(m_glob >> 5), ll = (int)(m_glob & 31);
#pragma unroll
    for (int mt = 0; mt < 4; mt++) {
        const int st = bb2 * 4 + mt;
        float4* dst = (float4*)g_gi + (((size_t)st * 32 + ll) * 24) * 32 + lid;
#pragma unroll
        for (int ntl = 0; ntl < 6; ntl++) {
            int nc = wn * 48 + ntl * 8 + tg * 2;
            int ntg = wn * 6 + ntl;
            float b0 = bias[nc], b1 = bias[nc + 1];
            float4 v = make_float4(acc[mt][ntl][0] + b0, acc[mt][ntl][1] + b1,
                                   acc[mt][ntl][2] + b0, acc[mt][ntl][3] + b1);
            dst[(size_t)ntg * 32] = v;
        }
    }
}

// ---------------------------------------------------------------------------
// k2b: tensor-core GRU + fused FC. grid=256 blocks x 128 thr (4 warps).
// Warp owns 16 seqs (seqtile st). Gates fully in registers via fragment align.
// smem: packedB tf32 frags 12288 f + h[4][16][68] fp32.
// ---------------------------------------------------------------------------
#define SMEMB ((12288 + 4 * 1088) * 4)

DEV float sigf(float x) { return 1.f / (1.f + expf(-x)); }

__global__ void __launch_bounds__(128) k2b_gru(const float* __restrict__ w_hh,
                                               const float* __restrict__ b_hh,
                                               const float* __restrict__ fc_w) {
    extern __shared__ __align__(16) float smb[];
    float* pb  = smb;              // 12288: packed B frags (tf32 bits)
    float* hws = smb + 12288;      // 4*1088

    const int tid = threadIdx.x;
    const int ws = tid >> 5, lid = tid & 31;
    const int g = lid >> 2, tg = lid & 3;
    float* hw = hws + ws * 1088;

    // build packed B fragments: pb[(kt*12+ntp)*128 + lane*4] =
    //   {b0(2ntp), b1(2ntp), b0(2ntp+1), b1(2ntp+1)} as tf32 bits
    for (int idx = tid; idx < 3072; idx += 128) {
        int kt = idx / 384, rem = idx % 384;
        int ntp = rem >> 5, l2 = rem & 31;
        int g2 = l2 >> 2, tg2 = l2 & 3;
        int k0 = kt * 8 + tg2;
        int n0 = (2 * ntp) * 8 + g2;
        int n1 = n0 + 8;
        float4 v;
        v.x = __uint_as_float(to_tf32(w_hh[n0 * 64 + k0]));
        v.y = __uint_as_float(to_tf32(w_hh[n0 * 64 + k0 + 4]));
        v.z = __uint_as_float(to_tf32(w_hh[n1 * 64 + k0]));
        v.w = __uint_as_float(to_tf32(w_hh[n1 * 64 + k0 + 4]));
        *(float4*)(pb + idx * 4) = v;
    }
    for (int i = tid; i < 4 * 1088; i += 128) hws[i] = 0.f;
    __syncthreads();

    const int st = blockIdx.x * 4 + ws;

    float bhn[8][2];
#pragma unroll
    for (int jt = 0; jt < 8; jt++) {
        bhn[jt][0] = b_hh[128 + jt * 8 + tg * 2];
        bhn[jt][1] = b_hh[128 + jt * 8 + tg * 2 + 1];
    }
    float hold[8][4];
#pragma unroll
    for (int jt = 0; jt < 8; jt++)
#pragma unroll
        for (int q = 0; q < 4; q++) hold[jt][q] = 0.f;

    const int sl = lid >> 1, ch = (lid & 1) * 32;
    const int n_g = (st * 16 + sl) & 63;
    const float* fwrow = fc_w + n_g * 2048 + ch;
    float fcacc = 0.f;

    const float4* gibase = (const float4*)g_gi + (size_t)st * 32 * 24 * 32 + lid;

    for (int l = 0; l < 32; l++) {
        // acc init from gi fragments (r,z) + b_hh_n (n)
        float acc[24][4];
        const float4* gl = gibase + (size_t)l * 24 * 32;
#pragma unroll
        for (int nt = 0; nt < 16; nt++) {
            float4 t = gl[(size_t)nt * 32];
            acc[nt][0] = t.x; acc[nt][1] = t.y; acc[nt][2] = t.z; acc[nt][3] = t.w;
        }
        float4 gin[8];
#pragma unroll
        for (int jt = 0; jt < 8; jt++) gin[jt] = gl[(size_t)(16 + jt) * 32];
#pragma unroll
        for (int jt = 0; jt < 8; jt++) {
            acc[16 + jt][0] = bhn[jt][0]; acc[16 + jt][1] = bhn[jt][1];
            acc[16 + jt][2] = bhn[jt][0]; acc[16 + jt][3] = bhn[jt][1];
        }
        // A-frags from h smem (fp32 -> tf32)
        uint32_t af[8][4];
#pragma unroll
        for (int kt = 0; kt < 8; kt++) {
            int c0 = kt * 8 + tg;
            af[kt][0] = to_tf32(hw[g * 68 + c0]);
            af[kt][1] = to_tf32(hw[(g + 8) * 68 + c0]);
            af[kt][2] = to_tf32(hw[g * 68 + c0 + 4]);
            af[kt][3] = to_tf32(hw[(g + 8) * 68 + c0 + 4]);
        }
        // mma: gh += h @ w_hh^T
#pragma unroll
        for (int kt = 0; kt < 8; kt++) {
#pragma unroll
            for (int ntp = 0; ntp < 12; ntp++) {
                float4 bp = *(const float4*)(pb + (kt * 12 + ntp) * 128 + lid * 4);
                uint32_t b0[2] = {__float_as_uint(bp.x), __float_as_uint(bp.y)};
                uint32_t b1[2] = {__float_as_uint(bp.z), __float_as_uint(bp.w)};
                mma8(acc[ntp * 2], af[kt], b0);
                mma8(acc[ntp * 2 + 1], af[kt], b1);
            }
        }
        // gates (registers only)
        float hnew[8][4];
#pragma unroll
        for (int jt = 0; jt < 8; jt++) {
            float gq[4] = {gin[jt].x, gin[jt].y, gin[jt].z, gin[jt].w};
#pragma unroll
            for (int q = 0; q < 4; q++) {
                float r = sigf(acc[jt][q]);
                float z = sigf(acc[jt + 8][q]);
                float n = tanhf(gq[q] + r * acc[jt + 16][q]);
                float hv = (1.f - z) * n + z * hold[jt][q];
                hnew[jt][q] = hv;
                hold[jt][q] = hv;
            }
        }
        __syncwarp();
#pragma unroll
        for (int jt = 0; jt < 8; jt++) {
            *(float2*)(hw + g * 68 + jt * 8 + tg * 2) =
                make_float2(hnew[jt][0], hnew[jt][1]);
            *(float2*)(hw + (g + 8) * 68 + jt * 8 + tg * 2) =
                make_float2(hnew[jt][2], hnew[jt][3]);
        }
        __syncwarp();
        // fused FC from smem h (lane remap: sl = lid>>1, 32-col half)
        const float* hrow = hw + sl * 68 + ch;
        const float* fw = fwrow + l * 64;
#pragma unroll
        for (int u = 0; u < 8; u++) {
            float4 hh = *(const float4*)(hrow + u * 4);
            float4 wf = *(const float4*)(fw + u * 4);
            fcacc += hh.x * wf.x + hh.y * wf.y + hh.z * wf.z + hh.w * wf.w;
        }
    }

#pragma unroll
    for (int o = 16; o > 0; o >>= 1)
        fcacc += __shfl_down_sync(0xffffffffu, fcacc, o);
    if (lid == 0) g_part[blockIdx.x * 4 + ws] = fcacc;
}

// ---------------------------------------------------------------------------
__global__ void k3_fc(const float* __restrict__ fc_b, float* __restrict__ out) {
    int b = threadIdx.x;
    float s = fc_b[0];
#pragma unroll
    for (int k = 0; k < 4; k++) s += g_part[b * 4 + k];
    out[b] = s;
}

// ---------------------------------------------------------------------------
extern "C" void kernel_launch(void* const* d_in, const int* in_sizes, int n_in,
                              void* d_out, int out_size) {
    const float* x    = (const float*)d_in[0];
    const float* filt = (const float*)d_in[1];
    const float* w_ih = (const float*)d_in[2];
    const float* w_hh = (const float*)d_in[3];
    const float* b_ih = (const float*)d_in[4];
    const float* b_hh = (const float*)d_in[5];
    const float* fc_w = (const float*)d_in[6];
    const float* fc_b = (const float*)d_in[7];
    float* out = (float*)d_out;

    const int SMEM1 = 17728 * 4;   // 70912 B
    cudaFuncSetAttribute(k1_cheb, cudaFuncAttributeMaxDynamicSharedMemorySize, SMEM1);
    cudaFuncSetAttribute(k2_gemm, cudaFuncAttributeMaxDynamicSharedMemorySize, SMEMG);
    cudaFuncSetAttribute(k2b_gru, cudaFuncAttributeMaxDynamicSharedMemorySize, SMEMB);

    k0_prepG<<<3, 192>>>(filt, w_ih);
    k1_cheb<<<8192, 256, SMEM1>>>(x);
    k2_gemm<<<4096, 256, SMEMG>>>(b_ih, b_hh);
    k2b_gru<<<256, 128, SMEMB>>>(w_hh, b_hh, fc_w);
    k3_fc<<<1, 256>>>(fc_b, out);
}

// round 6
// speedup vs baseline: 1.5935x; 1.0003x over previous
#include <cuda_runtime.h>
#include <math.h>
#include <stdint.h>

// ---------------------------------------------------------------------------
// STGNN R5:
//  k0_prepG : Gcat[192][192] = stack_k(F_k @ w_ih^T)
//  k1_cheb  : Gram(fp32) + exp + top8 -> sparse Cheb -> A=[Tx0|Tx1|Tx2] rows
//  k2_gemm  : gi = A @ Gcat + bias via mma.sync tf32, epilogue stores FRAGMENT
//             layout gi2[seqtile][l][ntile][lane]{4}; bias folds b_hh for r,z
//  k2b_gru  : tensor-core GRU: per-warp 16 seqs, gates in registers, fused FC
//  k3_fc    : final reduce
// ---------------------------------------------------------------------------

#define DEV static __device__ __forceinline__
typedef unsigned long long ull;

// device scratch (no allocations allowed)
__device__ float g_t[524288ull * 192];   // A rows: [m*64+n][192]
__device__ float g_gi[524288ull * 192];  // gi2 fragments: [(st*32+l)*24+nt][lane][4]
__device__ float g_G[192 * 192];         // Gcat
__device__ float g_part[1024];           // per-warp FC partials

DEV uint32_t to_tf32(float f) {
    uint32_t r;
    asm("cvt.rna.tf32.f32 %0, %1;" : "=r"(r) : "f"(f));
    return r;
}

DEV void mma8(float* c, const uint32_t* a, const uint32_t* b) {
    asm volatile(
        "mma.sync.aligned.m16n8k8.row.col.f32.tf32.tf32.f32 "
        "{%0,%1,%2,%3}, {%4,%5,%6,%7}, {%8,%9}, {%0,%1,%2,%3};"
        : "+f"(c[0]), "+f"(c[1]), "+f"(c[2]), "+f"(c[3])
        : "r"(a[0]), "r"(a[1]), "r"(a[2]), "r"(a[3]), "r"(b[0]), "r"(b[1]));
}

// ---------------- scalar FFMA2 GEMM helper (Gram) ----------------
union F4U { float4 f; ull u[2]; float s[4]; };
DEV ull pack2(float a) {
    ull r;
    asm("mov.b64 %0, {%1, %1};" : "=l"(r) : "r"(__float_as_uint(a)));
    return r;
}
DEV void fma2(ull& acc, ull a, ull b) {
    asm("fma.rn.f32x2 %0, %1, %2, %0;" : "+l"(acc) : "l"(a), "l"(b));
}
template <int LDA, int LDB>
DEV void mm64p(const float* A, const float* B, ull (&acc)[4][2], int i0, int j0) {
#pragma unroll 4
    for (int f = 0; f < 64; f += 4) {
        F4U a[4], bb[4];
#pragma unroll
        for (int r = 0; r < 4; r++)
            a[r].f = *(const float4*)(A + (i0 + r) * LDA + f);
#pragma unroll
        for (int k = 0; k < 4; k++)
            bb[k].f = *(const float4*)(B + (f + k) * LDB + j0);
#pragma unroll
        for (int k = 0; k < 4; k++) {
#pragma unroll
            for (int r = 0; r < 4; r++) {
                ull ad = pack2(a[r].s[k]);
                fma2(acc[r][0], ad, bb[k].u[0]);
                fma2(acc[r][1], ad, bb[k].u[1]);
            }
        }
    }
}
DEV void zacc(ull (&a)[4][2]) {
#pragma unroll
    for (int r = 0; r < 4; r++) { a[r][0] = 0ull; a[r][1] = 0ull; }
}

// ---------------------------------------------------------------------------
// k0: Gcat[(k*64+f)][j] = sum_h F[k][f][h] * w_ih[j][h].  grid=3, block=192.
// ---------------------------------------------------------------------------
__global__ void __launch_bounds__(192) k0_prepG(const float* __restrict__ filters,
                                                const float* __restrict__ w_ih) {
    __shared__ float Fs[4096];
    const int k = blockIdx.x, j = threadIdx.x;
    for (int i = j; i < 4096; i += 192) Fs[i] = filters[k * 4096 + i];
    float w[64];
#pragma unroll
    for (int h = 0; h < 64; h++) w[h] = w_ih[j * 64 + h];
    __syncthreads();
    for (int f = 0; f < 64; f++) {
        float s = 0.f;
#pragma unroll
        for (int h = 0; h < 64; h++) s = fmaf(Fs[f * 64 + h], w[h], s);
        g_G[(k * 64 + f) * 192 + j] = s;
    }
}

// ---------------------------------------------------------------------------
// k1: per-m: Gram(fp32) -> sim -> top8 -> sparse Tx1/Tx2 -> write A rows.
// grid=8192, block=256, smem 70912 B.
// ---------------------------------------------------------------------------
__global__ void __launch_bounds__(256) k1_cheb(const float* __restrict__ x) {
    extern __shared__ __align__(16) float sm1[];
    float* xs  = sm1;                 // 4096
    float* xsT = sm1 + 4096;          // 4352 (stride 68)
    float* adj = sm1 + 8448;          // 4096 (Gram -> sim)
    float* t1  = sm1 + 12544;         // 4096 (Tx1)
    float* sq  = sm1 + 16640;         // 64
    float* val = sm1 + 16704;         // 512
    int*   idx = (int*)(sm1 + 17216); // 512

    const int m = blockIdx.x;
    const int b = m >> 5, l = m & 31;
    const int tid = threadIdx.x;

    const float* xb = x + (size_t)b * 64 * 2048 + l * 64;
#pragma unroll
    for (int k = 0; k < 4; k++) {
        int v = tid + k * 256;
        int n = v >> 4, fo = (v & 15) << 2;
        *(float4*)(xs + n * 64 + fo) = *(const float4*)(xb + (size_t)n * 2048 + fo);
    }
    __syncthreads();

    for (int i = tid; i < 4096; i += 256) {
        int n = i >> 6, f = i & 63;
        xsT[f * 68 + n] = xs[i];
    }
    __syncthreads();

    const int tr = tid >> 4, tc = tid & 15;
    const int i0 = tr << 2, j0 = tc << 2;

    ull acc[4][2];
    zacc(acc);
    mm64p<64, 68>(xs, xsT, acc, i0, j0);
#pragma unroll
    for (int r = 0; r < 4; r++) {
        F4U o; o.u[0] = acc[r][0]; o.u[1] = acc[r][1];
        *(float4*)(adj + (i0 + r) * 64 + j0) = o.f;
    }
    __syncthreads();

    if (tid < 64) sq[tid] = adj[tid * 64 + tid];
    __syncthreads();

    for (int i = tid; i < 4096; i += 256) {
        int r = i >> 6, c = i & 63;
        float d2 = sq[r] + sq[c] - 2.f * adj[i];
        adj[i] = expf(-fmaxf(d2, 0.f));
    }
    __syncthreads();

    if (tid < 64) {
        float* row = adj + tid * 64;
        float tk[8];
#pragma unroll
        for (int i = 0; i < 8; i++) tk[i] = -1.f;
        for (int j = 0; j < 64; j++) {
            float v = row[j];
#pragma unroll
            for (int i = 0; i < 8; i++) {
                float mx = fmaxf(tk[i], v);
                v = fminf(tk[i], v);
                tk[i] = mx;
            }
        }
        float thr = tk[7];
        int cg = 0;
        for (int j = 0; j < 64; j++) cg += (row[j] > thr) ? 1 : 0;
        int rem = 8 - cg;
        int c = 0;
        for (int j = 0; j < 64; j++) {
            float v = row[j];
            bool take = false;
            if (v > thr) take = true;
            else if (v == thr && rem > 0) { take = true; rem--; }
            if (take) { val[tid * 8 + c] = v; idx[tid * 8 + c] = j; c++; }
        }
    }
    __syncthreads();

    const int row = tid >> 2, f0 = (tid & 3) << 4;
    float lv[8];
    int lj[8];
#pragma unroll
    for (int i = 0; i < 8; i++) { lv[i] = val[row * 8 + i]; lj[i] = idx[row * 8 + i]; }

    float4 a4[4];
#pragma unroll
    for (int q = 0; q < 4; q++) a4[q] = make_float4(0.f, 0.f, 0.f, 0.f);
#pragma unroll
    for (int i = 0; i < 8; i++) {
        float v = lv[i];
        const float4* xr = (const float4*)(xs + lj[i] * 64 + f0);
#pragma unroll
        for (int q = 0; q < 4; q++) {
            float4 t = xr[q];
            a4[q].x = fmaf(v, t.x, a4[q].x);
            a4[q].y = fmaf(v, t.y, a4[q].y);
            a4[q].z = fmaf(v, t.z, a4[q].z);
            a4[q].w = fmaf(v, t.w, a4[q].w);
        }
    }
#pragma unroll
    for (int q = 0; q < 4; q++) *(float4*)(t1 + row * 64 + f0 + q * 4) = a4[q];
    __syncthreads();

    float4 b4[4];
#pragma unroll
    for (int q = 0; q < 4; q++) b4[q] = make_float4(0.f, 0.f, 0.f, 0.f);
#pragma unroll
    for (int i = 0; i < 8; i++) {
        float v = lv[i];
        const float4* tr4 = (const float4*)(t1 + lj[i] * 64 + f0);
#pragma unroll
        for (int q = 0; q < 4; q++) {
            float4 t = tr4[q];
            b4[q].x = fmaf(v, t.x, b4[q].x);
            b4[q].y = fmaf(v, t.y, b4[q].y);
            b4[q].z = fmaf(v, t.z, b4[q].z);
            b4[q].w = fmaf(v, t.w, b4[q].w);
        }
    }

    float* dst = g_t + ((size_t)m * 64 + row) * 192;
#pragma unroll
    for (int q = 0; q < 4; q++) {
        float4 xv = *(const float4*)(xs + row * 64 + f0 + q * 4);
        *(float4*)(dst + f0 + q * 4) = xv;
        *(float4*)(dst + 64 + f0 + q * 4) = a4[q];
        float4 tn;
        tn.x = 2.f * b4[q].x - xv.x;
        tn.y = 2.f * b4[q].y - xv.y;
        tn.z = 2.f * b4[q].z - xv.z;
        tn.w = 2.f * b4[q].w - xv.w;
        *(float4*)(dst + 128 + f0 + q * 4) = tn;
    }
}

// ---------------------------------------------------------------------------
// k2: gi = A @ Gcat + bias via tf32 mma.sync. grid=4096, block=256 (8 warps).
// bias = b_ih + b_hh for cols<128 (r,z folded); epilogue: fragment layout.
// ---------------------------------------------------------------------------
#define LDA_S 36
#define LDB_S 200
#define SMEMG (22208 * 4)

__global__ void __launch_bounds__(256) k2_gemm(const float* __restrict__ b_ih,
                                               const float* __restrict__ b_hh) {
    extern __shared__ __align__(16) float smg[];
    float* A0   = smg;            // 9216
    float* B0   = smg + 9216;     // 12800
    float* bias = smg + 22016;    // 192

    const int tid = threadIdx.x;
    const int wid = tid >> 5, lid = tid & 31;
    const int g = lid >> 2, tg = lid & 3;
    const int wm = wid & 1, wn = wid >> 1;

    const size_t row0 = (size_t)blockIdx.x * 128;

    for (int i = tid; i < 192; i += 256)
        bias[i] = b_ih[i] + (i < 128 ? b_hh[i] : 0.f);

    float4 aR[4];
    float bR[24];
    auto ldg = [&](int c) {
#pragma unroll
        for (int t = 0; t < 4; t++) {
            int v = tid + (t << 8);
            int r = v >> 3, c4 = v & 7;
            aR[t] = *(const float4*)(g_t + (row0 + r) * 192 + c * 32 + c4 * 4);
        }
#pragma unroll
        for (int t = 0; t < 24; t++) {
            int e = tid + (t << 8);
            int kk = e / 192, n = e - kk * 192;
            bR[t] = g_G[(c * 32 + kk) * 192 + n];
        }
    };
    auto sts = [&](int buf) {
        uint32_t* ab = (uint32_t*)(A0 + buf * 4608);
        uint32_t* bb = (uint32_t*)(B0 + buf * 6400);
#pragma unroll
        for (int t = 0; t < 4; t++) {
            int v = tid + (t << 8);
            int r = v >> 3, c4 = v & 7;
            uint4 o;
            o.x = to_tf32(aR[t].x); o.y = to_tf32(aR[t].y);
            o.z = to_tf32(aR[t].z); o.w = to_tf32(aR[t].w);
            *(uint4*)(ab + r * LDA_S + c4 * 4) = o;
        }
#pragma unroll
        for (int t = 0; t < 24; t++) {
            int e = tid + (t << 8);
            int kk = e / 192, n = e - kk * 192;
            bb[kk * LDB_S + n] = to_tf32(bR[t]);
        }
    };

    float acc[4][6][4];
#pragma unroll
    for (int mt = 0; mt < 4; mt++)
#pragma unroll
        for (int nt = 0; nt < 6; nt++)
#pragma unroll
            for (int q = 0; q < 4; q++) acc[mt][nt][q] = 0.f;

    ldg(0);
    sts(0);
    __syncthreads();

    for (int c = 0; c < 6; c++) {
        if (c < 5) ldg(c + 1);
        const uint32_t* As = (const uint32_t*)(A0 + (c & 1) * 4608);
        const uint32_t* Bs = (const uint32_t*)(B0 + (c & 1) * 6400);
#pragma unroll
        for (int ks = 0; ks < 4; ks++) {
            const int kb = ks * 8;
            uint32_t af[4][4], bf[6][2];
#pragma unroll
            for (int mt = 0; mt < 4; mt++) {
                int mr = wm * 64 + mt * 16 + g;
                af[mt][0] = As[mr * LDA_S + kb + tg];
                af[mt][1] = As[(mr + 8) * LDA_S + kb + tg];
                af[mt][2] = As[mr * LDA_S + kb + tg + 4];
                af[mt][3] = As[(mr + 8) * LDA_S + kb + tg + 4];
            }
#pragma unroll
            for (int nt = 0; nt < 6; nt++) {
                int nc = wn * 48 + nt * 8 + g;
                bf[nt][0] = Bs[(kb + tg) * LDB_S + nc];
                bf[nt][1] = Bs[(kb + tg + 4) * LDB_S + nc];
            }
#pragma unroll
            for (int mt = 0; mt < 4; mt++)
#pragma unroll
                for (int nt = 0; nt < 6; nt++)
                    mma8(acc[mt][nt], af[mt], bf[nt]);
        }
        __syncthreads();
        if (c < 5) {
            sts((c + 1) & 1);
            __syncthreads();
        }
    }

    // epilogue: add bias, store FRAGMENT layout: gi2[((st*32+l)*24+nt)*32+lid]
    const size_t m_glob = (size_t)blockIdx.x * 2 + wm;
    const int bb2 = (int)(m_glob >> 5), ll = (int)(m_glob & 31);
#pragma unroll
    for (int mt = 0; mt < 4; mt++) {
        const int st = bb2 * 4 + mt;
        float4* dst = (float4*)g_gi + (((size_t)st * 32 + ll) * 24) * 32 + lid;
#pragma unroll
        for (int ntl = 0; ntl < 6; ntl++) {
            int nc = wn * 48 + ntl * 8 + tg * 2;
            int ntg = wn * 6 + ntl;
            float b0 = bias[nc], b1 = bias[nc + 1];
            float4 v = make_float4(acc[mt][ntl][0] + b0, acc[mt][ntl][1] + b1,
                                   acc[mt][ntl][2] + b0, acc[mt][ntl][3] + b1);
            dst[(size_t)ntg * 32] = v;
        }
    }
}

// ---------------------------------------------------------------------------
// k2b: tensor-core GRU + fused FC. grid=256 blocks x 128 thr (4 warps).
// Warp owns 16 seqs (seqtile st). Gates fully in registers via fragment align.
// smem: packedB tf32 frags 12288 f + h[4][16][68] fp32.
// ---------------------------------------------------------------------------
#define SMEMB ((12288 + 4 * 1088) * 4)

DEV float sigf(float x) { return 1.f / (1.f + expf(-x)); }

__global__ void __launch_bounds__(128) k2b_gru(const float* __restrict__ w_hh,
                                               const float* __restrict__ b_hh,
                                               const float* __restrict__ fc_w) {
    extern __shared__ __align__(16) float smb[];
    float* pb  = smb;              // 12288: packed B frags (tf32 bits)
    float* hws = smb + 12288;      // 4*1088

    const int tid = threadIdx.x;
    const int ws = tid >> 5, lid = tid & 31;
    const int g = lid >> 2, tg = lid & 3;
    float* hw = hws + ws * 1088;

    // build packed B fragments: pb[(kt*12+ntp)*128 + lane*4] =
    //   {b0(2ntp), b1(2ntp), b0(2ntp+1), b1(2ntp+1)} as tf32 bits
    for (int idx = tid; idx < 3072; idx += 128) {
        int kt = idx / 384, rem = idx % 384;
        int ntp = rem >> 5, l2 = rem & 31;
        int g2 = l2 >> 2, tg2 = l2 & 3;
        int k0 = kt * 8 + tg2;
        int n0 = (2 * ntp) * 8 + g2;
        int n1 = n0 + 8;
        float4 v;
        v.x = __uint_as_float(to_tf32(w_hh[n0 * 64 + k0]));
        v.y = __uint_as_float(to_tf32(w_hh[n0 * 64 + k0 + 4]));
        v.z = __uint_as_float(to_tf32(w_hh[n1 * 64 + k0]));
        v.w = __uint_as_float(to_tf32(w_hh[n1 * 64 + k0 + 4]));
        *(float4*)(pb + idx * 4) = v;
    }
    for (int i = tid; i < 4 * 1088; i += 128) hws[i] = 0.f;
    __syncthreads();

    const int st = blockIdx.x * 4 + ws;

    float bhn[8][2];
#pragma unroll
    for (int jt = 0; jt < 8; jt++) {
        bhn[jt][0] = b_hh[128 + jt * 8 + tg * 2];
        bhn[jt][1] = b_hh[128 + jt * 8 + tg * 2 + 1];
    }
    float hold[8][4];
#pragma unroll
    for (int jt = 0; jt < 8; jt++)
#pragma unroll
        for (int q = 0; q < 4; q++) hold[jt][q] = 0.f;

    const int sl = lid >> 1, ch = (lid & 1) * 32;
    const int n_g = (st * 16 + sl) & 63;
    const float* fwrow = fc_w + n_g * 2048 + ch;
    float fcacc = 0.f;

    const float4* gibase = (const float4*)g_gi + (size_t)st * 32 * 24 * 32 + lid;

    for (int l = 0; l < 32; l++) {
        // acc init from gi fragments (r,z) + b_hh_n (n)
        float acc[24][4];
        const float4* gl = gibase + (size_t)l * 24 * 32;
#pragma unroll
        for (int nt = 0; nt < 16; nt++) {
            float4 t = gl[(size_t)nt * 32];
            acc[nt][0] = t.x; acc[nt][1] = t.y; acc[nt][2] = t.z; acc[nt][3] = t.w;
        }
        float4 gin[8];
#pragma unroll
        for (int jt = 0; jt < 8; jt++) gin[jt] = gl[(size_t)(16 + jt) * 32];
#pragma unroll
        for (int jt = 0; jt < 8; jt++) {
            acc[16 + jt][0] = bhn[jt][0]; acc[16 + jt][1] = bhn[jt][1];
            acc[16 + jt][2] = bhn[jt][0]; acc[16 + jt][3] = bhn[jt][1];
        }
        // A-frags from h smem (fp32 -> tf32)
        uint32_t af[8][4];
#pragma unroll
        for (int kt = 0; kt < 8; kt++) {
            int c0 = kt * 8 + tg;
            af[kt][0] = to_tf32(hw[g * 68 + c0]);
            af[kt][1] = to_tf32(hw[(g + 8) * 68 + c0]);
            af[kt][2] = to_tf32(hw[g * 68 + c0 + 4]);
            af[kt][3] = to_tf32(hw[(g + 8) * 68 + c0 + 4]);
        }
        // mma: gh += h @ w_hh^T
#pragma unroll
        for (int kt = 0; kt < 8; kt++) {
#pragma unroll
            for (int ntp = 0; ntp < 12; ntp++) {
                float4 bp = *(const float4*)(pb + (kt * 12 + ntp) * 128 + lid * 4);
                uint32_t b0[2] = {__float_as_uint(bp.x), __float_as_uint(bp.y)};
                uint32_t b1[2] = {__float_as_uint(bp.z), __float_as_uint(bp.w)};
                mma8(acc[ntp * 2], af[kt], b0);
                mma8(acc[ntp * 2 + 1], af[kt], b1);
            }
        }
        // gates (registers only)
        float hnew[8][4];
#pragma unroll
        for (int jt = 0; jt < 8; jt++) {
            float gq[4] = {gin[jt].x, gin[jt].y, gin[jt].z, gin[jt].w};
#pragma unroll
            for (int q = 0; q < 4; q++) {
                float r = sigf(acc[jt][q]);
                float z = sigf(acc[jt + 8][q]);
                float n = tanhf(gq[q] + r * acc[jt + 16][q]);
                float hv = (1.f - z) * n + z * hold[jt][q];
                hnew[jt][q] = hv;
                hold[jt][q] = hv;
            }
        }
        __syncwarp();
#pragma unroll
        for (int jt = 0; jt < 8; jt++) {
            *(float2*)(hw + g * 68 + jt * 8 + tg * 2) =
                make_float2(hnew[jt][0], hnew[jt][1]);
            *(float2*)(hw + (g + 8) * 68 + jt * 8 + tg * 2) =
                make_float2(hnew[jt][2], hnew[jt][3]);
        }
        __syncwarp();
        // fused FC from smem h (lane remap: sl = lid>>1, 32-col half)
        const float* hrow = hw + sl * 68 + ch;
        const float* fw = fwrow + l * 64;
#pragma unroll
        for (int u = 0; u < 8; u++) {
            float4 hh = *(const float4*)(hrow + u * 4);
            float4 wf = *(const float4*)(fw + u * 4);
            fcacc += hh.x * wf.x + hh.y * wf.y + hh.z * wf.z + hh.w * wf.w;
        }
    }

#pragma unroll
    for (int o = 16; o > 0; o >>= 1)
        fcacc += __shfl_down_sync(0xffffffffu, fcacc, o);
    if (lid == 0) g_part[blockIdx.x * 4 + ws] = fcacc;
}

// ---------------------------------------------------------------------------
__global__ void k3_fc(const float* __restrict__ fc_b, float* __restrict__ out) {
    int b = threadIdx.x;
    float s = fc_b[0];
#pragma unroll
    for (int k = 0; k < 4; k++) s += g_part[b * 4 + k];
    out[b] = s;
}

// ---------------------------------------------------------------------------
extern "C" void kernel_launch(void* const* d_in, const int* in_sizes, int n_in,
                              void* d_out, int out_size) {
    const float* x    = (const float*)d_in[0];
    const float* filt = (const float*)d_in[1];
    const float* w_ih = (const float*)d_in[2];
    const float* w_hh = (const float*)d_in[3];
    const float* b_ih = (const float*)d_in[4];
    const float* b_hh = (const float*)d_in[5];
    const float* fc_w = (const float*)d_in[6];
    const float* fc_b = (const float*)d_in[7];
    float* out = (float*)d_out;

    const int SMEM1 = 17728 * 4;   // 70912 B
    cudaFuncSetAttribute(k1_cheb, cudaFuncAttributeMaxDynamicSharedMemorySize, SMEM1);
    cudaFuncSetAttribute(k2_gemm, cudaFuncAttributeMaxDynamicSharedMemorySize, SMEMG);
    cudaFuncSetAttribute(k2b_gru, cudaFuncAttributeMaxDynamicSharedMemorySize, SMEMB);

    k0_prepG<<<3, 192>>>(filt, w_ih);
    k1_cheb<<<8192, 256, SMEM1>>>(x);
    k2_gemm<<<4096, 256, SMEMG>>>(b_ih, b_hh);
    k2b_gru<<<256, 128, SMEMB>>>(w_hh, b_hh, fc_w);
    k3_fc<<<1, 256>>>(fc_b, out);
}

// round 7
// speedup vs baseline: 1.9481x; 1.2225x over previous
#include <cuda_runtime.h>
#include <math.h>
#include <stdint.h>

// ---------------------------------------------------------------------------
// STGNN R6:
//  k0_prepG : Gcat[192][192] = stack_k(F_k @ w_ih^T)
//  k1_cheb  : Gram via 3xtf32 mma (fp32-faithful) + conflict-free top-8
//             (adj stride 65) -> sparse Cheb -> A=[Tx0|Tx1|Tx2] rows
//  k2_gemm  : gi = A @ Gcat + bias via mma.sync tf32 -> fragment layout
//  k2b_gru  : tensor-core GRU, gates in registers, fused FC
//  k3_fc    : final reduce
// ---------------------------------------------------------------------------

#define DEV static __device__ __forceinline__
typedef unsigned long long ull;

// device scratch (no allocations allowed)
__device__ float g_t[524288ull * 192];   // A rows: [m*64+n][192]
__device__ float g_gi[524288ull * 192];  // gi2 fragments
__device__ float g_G[192 * 192];         // Gcat
__device__ float g_part[1024];           // per-warp FC partials

DEV uint32_t to_tf32(float f) {
    uint32_t r;
    asm("cvt.rna.tf32.f32 %0, %1;" : "=r"(r) : "f"(f));
    return r;
}

DEV void mma8(float* c, const uint32_t* a, const uint32_t* b) {
    asm volatile(
        "mma.sync.aligned.m16n8k8.row.col.f32.tf32.tf32.f32 "
        "{%0,%1,%2,%3}, {%4,%5,%6,%7}, {%8,%9}, {%0,%1,%2,%3};"
        : "+f"(c[0]), "+f"(c[1]), "+f"(c[2]), "+f"(c[3])
        : "r"(a[0]), "r"(a[1]), "r"(a[2]), "r"(a[3]), "r"(b[0]), "r"(b[1]));
}

// ---------------------------------------------------------------------------
// k0: Gcat[(k*64+f)][j] = sum_h F[k][f][h] * w_ih[j][h].  grid=3, block=192.
// ---------------------------------------------------------------------------
__global__ void __launch_bounds__(192) k0_prepG(const float* __restrict__ filters,
                                                const float* __restrict__ w_ih) {
    __shared__ float Fs[4096];
    const int k = blockIdx.x, j = threadIdx.x;
    for (int i = j; i < 4096; i += 192) Fs[i] = filters[k * 4096 + i];
    float w[64];
#pragma unroll
    for (int h = 0; h < 64; h++) w[h] = w_ih[j * 64 + h];
    __syncthreads();
    for (int f = 0; f < 64; f++) {
        float s = 0.f;
#pragma unroll
        for (int h = 0; h < 64; h++) s = fmaf(Fs[f * 64 + h], w[h], s);
        g_G[(k * 64 + f) * 192 + j] = s;
    }
}

// ---------------------------------------------------------------------------
// k1: per-m: Gram(3xtf32 mma) -> sim(__expf) -> top8 (stride-65, conflict
// free) -> sparse Tx1/Tx2 -> write A rows.  grid=8192, block=256.
// smem floats: xsp[64*68]=4352, adj[64*65]=4160, t1[64*68]=4352,
//              sq 64, val 512, idx 512  -> 13952 floats = 55808 B
// ---------------------------------------------------------------------------
#define SMEM1 (13952 * 4)

__global__ void __launch_bounds__(256) k1_cheb(const float* __restrict__ x) {
    extern __shared__ __align__(16) float sm1[];
    float* xsp = sm1;                  // stride 68
    float* adj = sm1 + 4352;           // stride 65
    float* t1  = sm1 + 8512;           // stride 68
    float* sq  = sm1 + 12864;          // 64
    float* val = sm1 + 12928;          // 512
    int*   idx = (int*)(sm1 + 13440);  // 512

    const int m = blockIdx.x;
    const int b = m >> 5, l = m & 31;
    const int tid = threadIdx.x;
    const int wid = tid >> 5, lid = tid & 31;
    const int g = lid >> 2, tg = lid & 3;

    // load xf[n][f] = x[(b*64+n)*2048 + l*64 + f] -> xsp (stride 68)
    const float* xb = x + (size_t)b * 64 * 2048 + l * 64;
#pragma unroll
    for (int k = 0; k < 4; k++) {
        int v = tid + k * 256;
        int n = v >> 4, fo = (v & 15) << 2;
        *(float4*)(xsp + n * 68 + fo) = *(const float4*)(xb + (size_t)n * 2048 + fo);
    }
    __syncthreads();

    // Gram = xs @ xs^T via 3xtf32 split mma. warp w: mt=w>>1, nt in [(w&1)*4, +4)
    {
        const int mt = wid >> 1, ntb = (wid & 1) * 4;
        float cacc[4][4];
#pragma unroll
        for (int t = 0; t < 4; t++)
#pragma unroll
            for (int q = 0; q < 4; q++) cacc[t][q] = 0.f;

#pragma unroll
        for (int kk = 0; kk < 8; kk++) {
            const int c0 = kk * 8 + tg, c1 = c0 + 4;
            const int r0 = mt * 16 + g, r1 = r0 + 8;
            float av[4] = {xsp[r0 * 68 + c0], xsp[r1 * 68 + c0],
                           xsp[r0 * 68 + c1], xsp[r1 * 68 + c1]};
            uint32_t ah[4], al[4];
#pragma unroll
            for (int q = 0; q < 4; q++) {
                ah[q] = to_tf32(av[q]);
                al[q] = to_tf32(av[q] - __uint_as_float(ah[q]));
            }
#pragma unroll
            for (int t = 0; t < 4; t++) {
                const int nr = (ntb + t) * 8 + g;
                float b0 = xsp[nr * 68 + c0], b1 = xsp[nr * 68 + c1];
                uint32_t bh[2], bl[2];
                bh[0] = to_tf32(b0); bl[0] = to_tf32(b0 - __uint_as_float(bh[0]));
                bh[1] = to_tf32(b1); bl[1] = to_tf32(b1 - __uint_as_float(bh[1]));
                mma8(cacc[t], ah, bl);
                mma8(cacc[t], al, bh);
                mma8(cacc[t], ah, bh);
            }
        }
#pragma unroll
        for (int t = 0; t < 4; t++) {
            const int col = (ntb + t) * 8 + tg * 2;
            const int r0 = mt * 16 + g;
            adj[r0 * 65 + col]       = cacc[t][0];
            adj[r0 * 65 + col + 1]   = cacc[t][1];
            adj[(r0 + 8) * 65 + col]     = cacc[t][2];
            adj[(r0 + 8) * 65 + col + 1] = cacc[t][3];
        }
    }
    __syncthreads();

    if (tid < 64) sq[tid] = adj[tid * 65 + tid];
    __syncthreads();

    // sim = exp(-max(sq_i + sq_j - 2*Gram, 0))
    for (int i = tid; i < 4096; i += 256) {
        int r = i >> 6, c = i & 63;
        float d2 = sq[r] + sq[c] - 2.f * adj[r * 65 + c];
        adj[r * 65 + c] = __expf(-fmaxf(d2, 0.f));
    }
    __syncthreads();

    // top-8 per row (stride 65 -> conflict-free), jax tie-break (earliest)
    if (tid < 64) {
        float* row = adj + tid * 65;
        float tk[8];
#pragma unroll
        for (int i = 0; i < 8; i++) tk[i] = -1.f;
        for (int j = 0; j < 64; j++) {
            float v = row[j];
#pragma unroll
            for (int i = 0; i < 8; i++) {
                float mx = fmaxf(tk[i], v);
                v = fminf(tk[i], v);
                tk[i] = mx;
            }
        }
        float thr = tk[7];
        int cg = 0;
        for (int j = 0; j < 64; j++) cg += (row[j] > thr) ? 1 : 0;
        int rem = 8 - cg;
        int c = 0;
        for (int j = 0; j < 64; j++) {
            float v = row[j];
            bool take = false;
            if (v > thr) take = true;
            else if (v == thr && rem > 0) { take = true; rem--; }
            if (take) { val[tid * 8 + c] = v; idx[tid * 8 + c] = j; c++; }
        }
    }
    __syncthreads();

    // sparse Cheb: 4 threads per row, 16 f-cols each
    const int row = tid >> 2, f0 = (tid & 3) << 4;
    float lv[8];
    int lj[8];
#pragma unroll
    for (int i = 0; i < 8; i++) { lv[i] = val[row * 8 + i]; lj[i] = idx[row * 8 + i]; }

    float4 a4[4];
#pragma unroll
    for (int q = 0; q < 4; q++) a4[q] = make_float4(0.f, 0.f, 0.f, 0.f);
#pragma unroll
    for (int i = 0; i < 8; i++) {
        float v = lv[i];
        const float4* xr = (const float4*)(xsp + lj[i] * 68 + f0);
#pragma unroll
        for (int q = 0; q < 4; q++) {
            float4 t = xr[q];
            a4[q].x = fmaf(v, t.x, a4[q].x);
            a4[q].y = fmaf(v, t.y, a4[q].y);
            a4[q].z = fmaf(v, t.z, a4[q].z);
            a4[q].w = fmaf(v, t.w, a4[q].w);
        }
    }
#pragma unroll
    for (int q = 0; q < 4; q++) *(float4*)(t1 + row * 68 + f0 + q * 4) = a4[q];
    __syncthreads();

    // Tx2 = 2*adj_sparse @ Tx1 - xs
    float4 b4[4];
#pragma unroll
    for (int q = 0; q < 4; q++) b4[q] = make_float4(0.f, 0.f, 0.f, 0.f);
#pragma unroll
    for (int i = 0; i < 8; i++) {
        float v = lv[i];
        const float4* tr4 = (const float4*)(t1 + lj[i] * 68 + f0);
#pragma unroll
        for (int q = 0; q < 4; q++) {
            float4 t = tr4[q];
            b4[q].x = fmaf(v, t.x, b4[q].x);
            b4[q].y = fmaf(v, t.y, b4[q].y);
            b4[q].z = fmaf(v, t.z, b4[q].z);
            b4[q].w = fmaf(v, t.w, b4[q].w);
        }
    }

    // write A row: [xs | Tx1 | Tx2]
    float* dst = g_t + ((size_t)m * 64 + row) * 192;
#pragma unroll
    for (int q = 0; q < 4; q++) {
        float4 xv = *(const float4*)(xsp + row * 68 + f0 + q * 4);
        *(float4*)(dst + f0 + q * 4) = xv;
        *(float4*)(dst + 64 + f0 + q * 4) = a4[q];
        float4 tn;
        tn.x = 2.f * b4[q].x - xv.x;
        tn.y = 2.f * b4[q].y - xv.y;
        tn.z = 2.f * b4[q].z - xv.z;
        tn.w = 2.f * b4[q].w - xv.w;
        *(float4*)(dst + 128 + f0 + q * 4) = tn;
    }
}

// ---------------------------------------------------------------------------
// k2: gi = A @ Gcat + bias via tf32 mma.sync. grid=4096, block=256 (8 warps).
// bias = b_ih + b_hh for cols<128 (r,z folded); epilogue: fragment layout.
// ---------------------------------------------------------------------------
#define LDA_S 36
#define LDB_S 200
#define SMEMG (22208 * 4)

__global__ void __launch_bounds__(256) k2_gemm(const float* __restrict__ b_ih,
                                               const float* __restrict__ b_hh) {
    extern __shared__ __align__(16) float smg[];
    float* A0   = smg;            // 9216
    float* B0   = smg + 9216;     // 12800
    float* bias = smg + 22016;    // 192

    const int tid = threadIdx.x;
    const int wid = tid >> 5, lid = tid & 31;
    const int g = lid >> 2, tg = lid & 3;
    const int wm = wid & 1, wn = wid >> 1;

    const size_t row0 = (size_t)blockIdx.x * 128;

    for (int i = tid; i < 192; i += 256)
        bias[i] = b_ih[i] + (i < 128 ? b_hh[i] : 0.f);

    float4 aR[4];
    float bR[24];
    auto ldg = [&](int c) {
#pragma unroll
        for (int t = 0; t < 4; t++) {
            int v = tid + (t << 8);
            int r = v >> 3, c4 = v & 7;
            aR[t] = *(const float4*)(g_t + (row0 + r) * 192 + c * 32 + c4 * 4);
        }
#pragma unroll
        for (int t = 0; t < 24; t++) {
            int e = tid + (t << 8);
            int kk = e / 192, n = e - kk * 192;
            bR[t] = g_G[(c * 32 + kk) * 192 + n];
        }
    };
    auto sts = [&](int buf) {
        uint32_t* ab = (uint32_t*)(A0 + buf * 4608);
        uint32_t* bb = (uint32_t*)(B0 + buf * 6400);
#pragma unroll
        for (int t = 0; t < 4; t++) {
            int v = tid + (t << 8);
            int r = v >> 3, c4 = v & 7;
            uint4 o;
            o.x = to_tf32(aR[t].x); o.y = to_tf32(aR[t].y);
            o.z = to_tf32(aR[t].z); o.w = to_tf32(aR[t].w);
            *(uint4*)(ab + r * LDA_S + c4 * 4) = o;
        }
#pragma unroll
        for (int t = 0; t < 24; t++) {
            int e = tid + (t << 8);
            int kk = e / 192, n = e - kk * 192;
            bb[kk * LDB_S + n] = to_tf32(bR[t]);
        }
    };

    float acc[4][6][4];
#pragma unroll
    for (int mt = 0; mt < 4; mt++)
#pragma unroll
        for (int nt = 0; nt < 6; nt++)
#pragma unroll
            for (int q = 0; q < 4; q++) acc[mt][nt][q] = 0.f;

    ldg(0);
    sts(0);
    __syncthreads();

    for (int c = 0; c < 6; c++) {
        if (c < 5) ldg(c + 1);
        const uint32_t* As = (const uint32_t*)(A0 + (c & 1) * 4608);
        const uint32_t* Bs = (const uint32_t*)(B0 + (c & 1) * 6400);
#pragma unroll
        for (int ks = 0; ks < 4; ks++) {
            const int kb = ks * 8;
            uint32_t af[4][4], bf[6][2];
#pragma unroll
            for (int mt = 0; mt < 4; mt++) {
                int mr = wm * 64 + mt * 16 + g;
                af[mt][0] = As[mr * LDA_S + kb + tg];
                af[mt][1] = As[(mr + 8) * LDA_S + kb + tg];
                af[mt][2] = As[mr * LDA_S + kb + tg + 4];
                af[mt][3] = As[(mr + 8) * LDA_S + kb + tg + 4];
            }
#pragma unroll
            for (int nt = 0; nt < 6; nt++) {
                int nc = wn * 48 + nt * 8 + g;
                bf[nt][0] = Bs[(kb + tg) * LDB_S + nc];
                bf[nt][1] = Bs[(kb + tg + 4) * LDB_S + nc];
            }
#pragma unroll
            for (int mt = 0; mt < 4; mt++)
#pragma unroll
                for (int nt = 0; nt < 6; nt++)
                    mma8(acc[mt][nt], af[mt], bf[nt]);
        }
        __syncthreads();
        if (c < 5) {
            sts((c + 1) & 1);
            __syncthreads();
        }
    }

    // epilogue: add bias, store FRAGMENT layout: gi2[((st*32+l)*24+nt)*32+lid]
    const size_t m_glob = (size_t)blockIdx.x * 2 + wm;
    const int bb2 = (int)(m_glob >> 5), ll = (int)(m_glob & 31);
#pragma unroll
    for (int mt = 0; mt < 4; mt++) {
        const int st = bb2 * 4 + mt;
        float4* dst = (float4*)g_gi + (((size_t)st * 32 + ll) * 24) * 32 + lid;
#pragma unroll
        for (int ntl = 0; ntl < 6; ntl++) {
            int nc = wn * 48 + ntl * 8 + tg * 2;
            int ntg = wn * 6 + ntl;
            float b0 = bias[nc], b1 = bias[nc + 1];
            float4 v = make_float4(acc[mt][ntl][0] + b0, acc[mt][ntl][1] + b1,
                                   acc[mt][ntl][2] + b0, acc[mt][ntl][3] + b1);
            dst[(size_t)ntg * 32] = v;
        }
    }
}

// ---------------------------------------------------------------------------
// k2b: tensor-core GRU + fused FC. grid=256 blocks x 128 thr (4 warps).
// ---------------------------------------------------------------------------
#define SMEMB ((12288 + 4 * 1088) * 4)

DEV float sigf(float x) { return 1.f / (1.f + expf(-x)); }

__global__ void __launch_bounds__(128) k2b_gru(const float* __restrict__ w_hh,
                                               const float* __restrict__ b_hh,
                                               const float* __restrict__ fc_w) {
    extern __shared__ __align__(16) float smb[];
    float* pb  = smb;              // 12288: packed B frags (tf32 bits)
    float* hws = smb + 12288;      // 4*1088

    const int tid = threadIdx.x;
    const int ws = tid >> 5, lid = tid & 31;
    const int g = lid >> 2, tg = lid & 3;
    float* hw = hws + ws * 1088;

    for (int idx = tid; idx < 3072; idx += 128) {
        int kt = idx / 384, rem = idx % 384;
        int ntp = rem >> 5, l2 = rem & 31;
        int g2 = l2 >> 2, tg2 = l2 & 3;
        int k0 = kt * 8 + tg2;
        int n0 = (2 * ntp) * 8 + g2;
        int n1 = n0 + 8;
        float4 v;
        v.x = __uint_as_float(to_tf32(w_hh[n0 * 64 + k0]));
        v.y = __uint_as_float(to_tf32(w_hh[n0 * 64 + k0 + 4]));
        v.z = __uint_as_float(to_tf32(w_hh[n1 * 64 + k0]));
        v.w = __uint_as_float(to_tf32(w_hh[n1 * 64 + k0 + 4]));
        *(float4*)(pb + idx * 4) = v;
    }
    for (int i = tid; i < 4 * 1088; i += 128) hws[i] = 0.f;
    __syncthreads();

    const int st = blockIdx.x * 4 + ws;

    float bhn[8][2];
#pragma unroll
    for (int jt = 0; jt < 8; jt++) {
        bhn[jt][0] = b_hh[128 + jt * 8 + tg * 2];
        bhn[jt][1] = b_hh[128 + jt * 8 + tg * 2 + 1];
    }
    float hold[8][4];
#pragma unroll
    for (int jt = 0; jt < 8; jt++)
#pragma unroll
        for (int q = 0; q < 4; q++) hold[jt][q] = 0.f;

    const int sl = lid >> 1, ch = (lid & 1) * 32;
    const int n_g = (st * 16 + sl) & 63;
    const float* fwrow = fc_w + n_g * 2048 + ch;
    float fcacc = 0.f;

    const float4* gibase = (const float4*)g_gi + (size_t)st * 32 * 24 * 32 + lid;

    for (int l = 0; l < 32; l++) {
        float acc[24][4];
        const float4* gl = gibase + (size_t)l * 24 * 32;
#pragma unroll
        for (int nt = 0; nt < 16; nt++) {
            float4 t = gl[(size_t)nt * 32];
            acc[nt][0] = t.x; acc[nt][1] = t.y; acc[nt][2] = t.z; acc[nt][3] = t.w;
        }
        float4 gin[8];
#pragma unroll
        for (int jt = 0; jt < 8; jt++) gin[jt] = gl[(size_t)(16 + jt) * 32];
#pragma unroll
        for (int jt = 0; jt < 8; jt++) {
            acc[16 + jt][0] = bhn[jt][0]; acc[16 + jt][1] = bhn[jt][1];
            acc[16 + jt][2] = bhn[jt][0]; acc[16 + jt][3] = bhn[jt][1];
        }
        uint32_t af[8][4];
#pragma unroll
        for (int kt = 0; kt < 8; kt++) {
            int c0 = kt * 8 + tg;
            af[kt][0] = to_tf32(hw[g * 68 + c0]);
            af[kt][1] = to_tf32(hw[(g + 8) * 68 + c0]);
            af[kt][2] = to_tf32(hw[g * 68 + c0 + 4]);
            af[kt][3] = to_tf32(hw[(g + 8) * 68 + c0 + 4]);
        }
#pragma unroll
        for (int kt = 0; kt < 8; kt++) {
#pragma unroll
            for (int ntp = 0; ntp < 12; ntp++) {
                float4 bp = *(const float4*)(pb + (kt * 12 + ntp) * 128 + lid * 4);
                uint32_t b0[2] = {__float_as_uint(bp.x), __float_as_uint(bp.y)};
                uint32_t b1[2] = {__float_as_uint(bp.z), __float_as_uint(bp.w)};
                mma8(acc[ntp * 2], af[kt], b0);
                mma8(acc[ntp * 2 + 1], af[kt], b1);
            }
        }
        float hnew[8][4];
#pragma unroll
        for (int jt = 0; jt < 8; jt++) {
            float gq[4] = {gin[jt].x, gin[jt].y, gin[jt].z, gin[jt].w};
#pragma unroll
            for (int q = 0; q < 4; q++) {
                float r = sigf(acc[jt][q]);
                float z = sigf(acc[jt + 8][q]);
                float n = tanhf(gq[q] + r * acc[jt + 16][q]);
                float hv = (1.f - z) * n + z * hold[jt][q];
                hnew[jt][q] = hv;
                hold[jt][q] = hv;
            }
        }
        __syncwarp();
#pragma unroll
        for (int jt = 0; jt < 8; jt++) {
            *(float2*)(hw + g * 68 + jt * 8 + tg * 2) =
                make_float2(hnew[jt][0], hnew[jt][1]);
            *(float2*)(hw + (g + 8) * 68 + jt * 8 + tg * 2) =
                make_float2(hnew[jt][2], hnew[jt][3]);
        }
        __syncwarp();
        const float* hrow = hw + sl * 68 + ch;
        const float* fw = fwrow + l * 64;
#pragma unroll
        for (int u = 0; u < 8; u++) {
            float4 hh = *(const float4*)(hrow + u * 4);
            float4 wf = *(const float4*)(fw + u * 4);
            fcacc += hh.x * wf.x + hh.y * wf.y + hh.z * wf.z + hh.w * wf.w;
        }
    }

#pragma unroll
    for (int o = 16; o > 0; o >>= 1)
        fcacc += __shfl_down_sync(0xffffffffu, fcacc, o);
    if (lid == 0) g_part[blockIdx.x * 4 + ws] = fcacc;
}

// ---------------------------------------------------------------------------
__global__ void k3_fc(const float* __restrict__ fc_b, float* __restrict__ out) {
    int b = threadIdx.x;
    float s = fc_b[0];
#pragma unroll
    for (int k = 0; k < 4; k++) s += g_part[b * 4 + k];
    out[b] = s;
}

// ---------------------------------------------------------------------------
extern "C" void kernel_launch(void* const* d_in, const int* in_sizes, int n_in,
                              void* d_out, int out_size) {
    const float* x    = (const float*)d_in[0];
    const float* filt = (const float*)d_in[1];
    const float* w_ih = (const float*)d_in[2];
    const float* w_hh = (const float*)d_in[3];
    const float* b_ih = (const float*)d_in[4];
    const float* b_hh = (const float*)d_in[5];
    const float* fc_w = (const float*)d_in[6];
    const float* fc_b = (const float*)d_in[7];
    float* out = (float*)d_out;

    cudaFuncSetAttribute(k1_cheb, cudaFuncAttributeMaxDynamicSharedMemorySize, SMEM1);
    cudaFuncSetAttribute(k2_gemm, cudaFuncAttributeMaxDynamicSharedMemorySize, SMEMG);
    cudaFuncSetAttribute(k2b_gru, cudaFuncAttributeMaxDynamicSharedMemorySize, SMEMB);

    k0_prepG<<<3, 192>>>(filt, w_ih);
    k1_cheb<<<8192, 256, SMEM1>>>(x);
    k2_gemm<<<4096, 256, SMEMG>>>(b_ih, b_hh);
    k2b_gru<<<256, 128, SMEMB>>>(w_hh, b_hh, fc_w);
    k3_fc<<<1, 256>>>(fc_b, out);
}

// round 9
// speedup vs baseline: 2.1907x; 1.1245x over previous
#include <cuda_runtime.h>
#include <math.h>
#include <stdint.h>

// ---------------------------------------------------------------------------
// STGNN R9 (R7 fused design, smem layout fixed):
//  k0_prepG : Gcat[192][192] = stack_k(F_k @ w_ih^T)
//  k0b_pack : Gcat -> B-fragment table (tf32) + folded bias
//  k1_fused : Gram(3xtf32) -> top8 -> sparse Cheb -> gi GEMM (mma.sync tf32)
//             -> fragment-layout gi stores.
//  k2b_gru  : tensor-core GRU, gates in registers, fused FC
//  k3_fc    : final reduce
// ---------------------------------------------------------------------------

#define DEV static __device__ __forceinline__
typedef unsigned long long ull;

// device scratch (no allocations allowed)
__device__ float g_gi[524288ull * 192];  // gi fragments: [(st*32+l)*24+nt][lane][4]
__device__ float g_G[192 * 192];         // Gcat
__device__ float g_Gf[24 * 24 * 32 * 2]; // B fragments: [kk][nt][lane]{2} tf32 bits
__device__ float g_bias[192];            // b_ih + b_hh (cols<128)
__device__ float g_part[1024];           // per-warp FC partials

DEV uint32_t to_tf32(float f) {
    uint32_t r;
    asm("cvt.rna.tf32.f32 %0, %1;" : "=r"(r) : "f"(f));
    return r;
}

DEV void mma8(float* c, const uint32_t* a, const uint32_t* b) {
    asm volatile(
        "mma.sync.aligned.m16n8k8.row.col.f32.tf32.tf32.f32 "
        "{%0,%1,%2,%3}, {%4,%5,%6,%7}, {%8,%9}, {%0,%1,%2,%3};"
        : "+f"(c[0]), "+f"(c[1]), "+f"(c[2]), "+f"(c[3])
        : "r"(a[0]), "r"(a[1]), "r"(a[2]), "r"(a[3]), "r"(b[0]), "r"(b[1]));
}

// ---------------------------------------------------------------------------
// k0: Gcat[(k*64+f)][j] = sum_h F[k][f][h] * w_ih[j][h].  grid=3, block=192.
// ---------------------------------------------------------------------------
__global__ void __launch_bounds__(192) k0_prepG(const float* __restrict__ filters,
                                                const float* __restrict__ w_ih) {
    __shared__ float Fs[4096];
    const int k = blockIdx.x, j = threadIdx.x;
    for (int i = j; i < 4096; i += 192) Fs[i] = filters[k * 4096 + i];
    float w[64];
#pragma unroll
    for (int h = 0; h < 64; h++) w[h] = w_ih[j * 64 + h];
    __syncthreads();
    for (int f = 0; f < 64; f++) {
        float s = 0.f;
#pragma unroll
        for (int h = 0; h < 64; h++) s = fmaf(Fs[f * 64 + h], w[h], s);
        g_G[(k * 64 + f) * 192 + j] = s;
    }
}

// ---------------------------------------------------------------------------
// k0b: pack Gcat into mma B-fragment layout + folded bias. grid=24, block=256.
// ---------------------------------------------------------------------------
__global__ void __launch_bounds__(256) k0b_pack(const float* __restrict__ b_ih,
                                                const float* __restrict__ b_hh) {
    const int tid = threadIdx.x, kk = blockIdx.x;
    if (kk == 0 && tid < 192)
        g_bias[tid] = b_ih[tid] + (tid < 128 ? b_hh[tid] : 0.f);
    for (int i = tid; i < 768; i += 256) {
        int nt = i >> 5, lid = i & 31;
        int g = lid >> 2, tg = lid & 3;
        float v0 = g_G[(kk * 8 + tg) * 192 + nt * 8 + g];
        float v1 = g_G[(kk * 8 + tg + 4) * 192 + nt * 8 + g];
        g_Gf[((kk * 24 + nt) * 32 + lid) * 2]     = __uint_as_float(to_tf32(v0));
        g_Gf[((kk * 24 + nt) * 32 + lid) * 2 + 1] = __uint_as_float(to_tf32(v1));
    }
}

// ---------------------------------------------------------------------------
// k1_fused: grid=8192, block=256.
// smem layout (floats):
//   xsp 0      .. 4352   (64 x stride 68)
//   adj 4352   .. 8512   (64 x stride 65)
//   t1  8512   .. 12864  (64 x stride 68)
//   t2  12864  .. 17216  (64 x stride 68)
//   sq  17216  .. 17280
//   val 17280  .. 17792
//   idx 17792  .. 18304
// total 18304 floats = 73216 B
// ---------------------------------------------------------------------------
#define SMEM1 (18304 * 4)

__global__ void __launch_bounds__(256) k1_fused(const float* __restrict__ x) {
    extern __shared__ __align__(16) float sm1[];
    float* xsp = sm1;
    float* adj = sm1 + 4352;
    float* t1  = sm1 + 8512;
    float* t2  = sm1 + 12864;
    float* sq  = sm1 + 17216;
    float* val = sm1 + 17280;
    int*   idx = (int*)(sm1 + 17792);

    const int m = blockIdx.x;
    const int b = m >> 5, l = m & 31;
    const int tid = threadIdx.x;
    const int wid = tid >> 5, lid = tid & 31;
    const int g = lid >> 2, tg = lid & 3;

    // load xf[n][f] -> xsp (stride 68)
    const float* xb = x + (size_t)b * 64 * 2048 + l * 64;
#pragma unroll
    for (int k = 0; k < 4; k++) {
        int v = tid + k * 256;
        int n = v >> 4, fo = (v & 15) << 2;
        *(float4*)(xsp + n * 68 + fo) = *(const float4*)(xb + (size_t)n * 2048 + fo);
    }
    __syncthreads();

    // Gram = xs @ xs^T via 3xtf32 split mma. warp w: mt=w>>1, nt in [(w&1)*4,+4)
    {
        const int mt = wid >> 1, ntb = (wid & 1) * 4;
        float cacc[4][4];
#pragma unroll
        for (int t = 0; t < 4; t++)
#pragma unroll
            for (int q = 0; q < 4; q++) cacc[t][q] = 0.f;

#pragma unroll
        for (int kk = 0; kk < 8; kk++) {
            const int c0 = kk * 8 + tg, c1 = c0 + 4;
            const int r0 = mt * 16 + g, r1 = r0 + 8;
            float av[4] = {xsp[r0 * 68 + c0], xsp[r1 * 68 + c0],
                           xsp[r0 * 68 + c1], xsp[r1 * 68 + c1]};
            uint32_t ah[4], al[4];
#pragma unroll
            for (int q = 0; q < 4; q++) {
                ah[q] = to_tf32(av[q]);
                al[q] = to_tf32(av[q] - __uint_as_float(ah[q]));
            }
#pragma unroll
            for (int t = 0; t < 4; t++) {
                const int nr = (ntb + t) * 8 + g;
                float b0 = xsp[nr * 68 + c0], b1 = xsp[nr * 68 + c1];
                uint32_t bh[2], bl[2];
                bh[0] = to_tf32(b0); bl[0] = to_tf32(b0 - __uint_as_float(bh[0]));
                bh[1] = to_tf32(b1); bl[1] = to_tf32(b1 - __uint_as_float(bh[1]));
                mma8(cacc[t], ah, bl);
                mma8(cacc[t], al, bh);
                mma8(cacc[t], ah, bh);
            }
        }
#pragma unroll
        for (int t = 0; t < 4; t++) {
            const int col = (ntb + t) * 8 + tg * 2;
            const int r0 = mt * 16 + g;
            adj[r0 * 65 + col]           = cacc[t][0];
            adj[r0 * 65 + col + 1]       = cacc[t][1];
            adj[(r0 + 8) * 65 + col]     = cacc[t][2];
            adj[(r0 + 8) * 65 + col + 1] = cacc[t][3];
        }
    }
    __syncthreads();

    if (tid < 64) sq[tid] = adj[tid * 65 + tid];
    __syncthreads();

    for (int i = tid; i < 4096; i += 256) {
        int r = i >> 6, c = i & 63;
        float d2 = sq[r] + sq[c] - 2.f * adj[r * 65 + c];
        adj[r * 65 + c] = __expf(-fmaxf(d2, 0.f));
    }
    __syncthreads();

    // top-8 per row (stride 65 -> conflict-free), jax tie-break (earliest)
    if (tid < 64) {
        float* row = adj + tid * 65;
        float tk[8];
#pragma unroll
        for (int i = 0; i < 8; i++) tk[i] = -1.f;
        for (int j = 0; j < 64; j++) {
            float v = row[j];
#pragma unroll
            for (int i = 0; i < 8; i++) {
                float mx = fmaxf(tk[i], v);
                v = fminf(tk[i], v);
                tk[i] = mx;
            }
        }
        float thr = tk[7];
        int cg = 0;
        for (int j = 0; j < 64; j++) cg += (row[j] > thr) ? 1 : 0;
        int rem = 8 - cg;
        int c = 0;
        for (int j = 0; j < 64; j++) {
            float v = row[j];
            bool take = false;
            if (v > thr) take = true;
            else if (v == thr && rem > 0) { take = true; rem--; }
            if (take) { val[tid * 8 + c] = v; idx[tid * 8 + c] = j; c++; }
        }
    }
    __syncthreads();

    // sparse Cheb: 4 threads per row, 16 f-cols each
    const int row = tid >> 2, f0 = (tid & 3) << 4;
    float lv[8];
    int lj[8];
#pragma unroll
    for (int i = 0; i < 8; i++) { lv[i] = val[row * 8 + i]; lj[i] = idx[row * 8 + i]; }

    float4 a4[4];
#pragma unroll
    for (int q = 0; q < 4; q++) a4[q] = make_float4(0.f, 0.f, 0.f, 0.f);
#pragma unroll
    for (int i = 0; i < 8; i++) {
        float v = lv[i];
        const float4* xr = (const float4*)(xsp + lj[i] * 68 + f0);
#pragma unroll
        for (int q = 0; q < 4; q++) {
            float4 t = xr[q];
            a4[q].x = fmaf(v, t.x, a4[q].x);
            a4[q].y = fmaf(v, t.y, a4[q].y);
            a4[q].z = fmaf(v, t.z, a4[q].z);
            a4[q].w = fmaf(v, t.w, a4[q].w);
        }
    }
#pragma unroll
    for (int q = 0; q < 4; q++) *(float4*)(t1 + row * 68 + f0 + q * 4) = a4[q];
    __syncthreads();

    // Tx2 = 2*adj_sparse @ Tx1 - xs  -> t2
    float4 b4[4];
#pragma unroll
    for (int q = 0; q < 4; q++) b4[q] = make_float4(0.f, 0.f, 0.f, 0.f);
#pragma unroll
    for (int i = 0; i < 8; i++) {
        float v = lv[i];
        const float4* tr4 = (const float4*)(t1 + lj[i] * 68 + f0);
#pragma unroll
        for (int q = 0; q < 4; q++) {
            float4 t = tr4[q];
            b4[q].x = fmaf(v, t.x, b4[q].x);
            b4[q].y = fmaf(v, t.y, b4[q].y);
            b4[q].z = fmaf(v, t.z, b4[q].z);
            b4[q].w = fmaf(v, t.w, b4[q].w);
        }
    }
#pragma unroll
    for (int q = 0; q < 4; q++) {
        float4 xv = *(const float4*)(xsp + row * 68 + f0 + q * 4);
        float4 tn;
        tn.x = 2.f * b4[q].x - xv.x;
        tn.y = 2.f * b4[q].y - xv.y;
        tn.z = 2.f * b4[q].z - xv.z;
        tn.w = 2.f * b4[q].w - xv.w;
        *(float4*)(t2 + row * 68 + f0 + q * 4) = tn;
    }
    __syncthreads();

    // ---- gi GEMM: gi = [xsp|t1|t2] @ Gcat + bias, mma tf32 ----
    // warp w: mt = w&3 (16 rows), nh = w>>2 (12 ntiles)
    const int mt = wid & 3, nh = wid >> 2;
    float acc[12][4];
#pragma unroll
    for (int nt = 0; nt < 12; nt++)
#pragma unroll
        for (int q = 0; q < 4; q++) acc[nt][q] = 0.f;

    const int r0 = mt * 16 + g;
#pragma unroll
    for (int kk = 0; kk < 24; kk++) {
        const float* Abuf = (kk < 8) ? xsp : ((kk < 16) ? t1 : t2);
        const int c0 = (kk & 7) * 8 + tg;
        uint32_t af[4];
        af[0] = to_tf32(Abuf[r0 * 68 + c0]);
        af[1] = to_tf32(Abuf[(r0 + 8) * 68 + c0]);
        af[2] = to_tf32(Abuf[r0 * 68 + c0 + 4]);
        af[3] = to_tf32(Abuf[(r0 + 8) * 68 + c0 + 4]);
        const float2* Bf = (const float2*)g_Gf + ((size_t)kk * 24 + nh * 12) * 32 + lid;
#pragma unroll
        for (int nt = 0; nt < 12; nt++) {
            float2 bv = Bf[(size_t)nt * 32];
            uint32_t bf2[2] = {__float_as_uint(bv.x), __float_as_uint(bv.y)};
            mma8(acc[nt], af, bf2);
        }
    }

    // epilogue: add bias, fragment-layout store
    const int st = b * 4 + mt;
    float4* dst = (float4*)g_gi + (((size_t)st * 32 + l) * 24 + nh * 12) * 32 + lid;
#pragma unroll
    for (int nt = 0; nt < 12; nt++) {
        const int ntg = nh * 12 + nt;
        float b0 = g_bias[ntg * 8 + tg * 2];
        float b1 = g_bias[ntg * 8 + tg * 2 + 1];
        dst[(size_t)nt * 32] = make_float4(acc[nt][0] + b0, acc[nt][1] + b1,
                                           acc[nt][2] + b0, acc[nt][3] + b1);
    }
}

// ---------------------------------------------------------------------------
// k2b: tensor-core GRU + fused FC. grid=256 blocks x 128 thr (4 warps).
// ---------------------------------------------------------------------------
#define SMEMB ((12288 + 4 * 1088) * 4)

DEV float sigf(float x) { return 1.f / (1.f + expf(-x)); }

__global__ void __launch_bounds__(128) k2b_gru(const float* __restrict__ w_hh,
                                               const float* __restrict__ b_hh,
                                               const float* __restrict__ fc_w) {
    extern __shared__ __align__(16) float smb[];
    float* pb  = smb;              // 12288: packed B frags (tf32 bits)
    float* hws = smb + 12288;      // 4*1088

    const int tid = threadIdx.x;
    const int ws = tid >> 5, lid = tid & 31;
    const int g = lid >> 2, tg = lid & 3;
    float* hw = hws + ws * 1088;

    for (int idx = tid; idx < 3072; idx += 128) {
        int kt = idx / 384, rem = idx % 384;
        int ntp = rem >> 5, l2 = rem & 31;
        int g2 = l2 >> 2, tg2 = l2 & 3;
        int k0 = kt * 8 + tg2;
        int n0 = (2 * ntp) * 8 + g2;
        int n1 = n0 + 8;
        float4 v;
        v.x = __uint_as_float(to_tf32(w_hh[n0 * 64 + k0]));
        v.y = __uint_as_float(to_tf32(w_hh[n0 * 64 + k0 + 4]));
        v.z = __uint_as_float(to_tf32(w_hh[n1 * 64 + k0]));
        v.w = __uint_as_float(to_tf32(w_hh[n1 * 64 + k0 + 4]));
        *(float4*)(pb + idx * 4) = v;
    }
    for (int i = tid; i < 4 * 1088; i += 128) hws[i] = 0.f;
    __syncthreads();

    const int st = blockIdx.x * 4 + ws;

    float bhn[8][2];
#pragma unroll
    for (int jt = 0; jt < 8; jt++) {
        bhn[jt][0] = b_hh[128 + jt * 8 + tg * 2];
        bhn[jt][1] = b_hh[128 + jt * 8 + tg * 2 + 1];
    }
    float hold[8][4];
#pragma unroll
    for (int jt = 0; jt < 8; jt++)
#pragma unroll
        for (int q = 0; q < 4; q++) hold[jt][q] = 0.f;

    const int sl = lid >> 1, ch = (lid & 1) * 32;
    const int n_g = (st * 16 + sl) & 63;
    const float* fwrow = fc_w + n_g * 2048 + ch;
    float fcacc = 0.f;

    const float4* gibase = (const float4*)g_gi + (size_t)st * 32 * 24 * 32 + lid;

    for (int l = 0; l < 32; l++) {
        float acc[24][4];
        const float4* gl = gibase + (size_t)l * 24 * 32;
#pragma unroll
        for (int nt = 0; nt < 16; nt++) {
            float4 t = gl[(size_t)nt * 32];
            acc[nt][0] = t.x; acc[nt][1] = t.y; acc[nt][2] = t.z; acc[nt][3] = t.w;
        }
        float4 gin[8];
#pragma unroll
        for (int jt = 0; jt < 8; jt++) gin[jt] = gl[(size_t)(16 + jt) * 32];
#pragma unroll
        for (int jt = 0; jt < 8; jt++) {
            acc[16 + jt][0] = bhn[jt][0]; acc[16 + jt][1] = bhn[jt][1];
            acc[16 + jt][2] = bhn[jt][0]; acc[16 + jt][3] = bhn[jt][1];
        }
        uint32_t af[8][4];
#pragma unroll
        for (int kt = 0; kt < 8; kt++) {
            int c0 = kt * 8 + tg;
            af[kt][0] = to_tf32(hw[g * 68 + c0]);
            af[kt][1] = to_tf32(hw[(g + 8) * 68 + c0]);
            af[kt][2] = to_tf32(hw[g * 68 + c0 + 4]);
            af[kt][3] = to_tf32(hw[(g + 8) * 68 + c0 + 4]);
        }
#pragma unroll
        for (int kt = 0; kt < 8; kt++) {
#pragma unroll
            for (int ntp = 0; ntp < 12; ntp++) {
                float4 bp = *(const float4*)(pb + (kt * 12 + ntp) * 128 + lid * 4);
                uint32_t b0[2] = {__float_as_uint(bp.x), __float_as_uint(bp.y)};
                uint32_t b1[2] = {__float_as_uint(bp.z), __float_as_uint(bp.w)};
                mma8(acc[ntp * 2], af[kt], b0);
                mma8(acc[ntp * 2 + 1], af[kt], b1);
            }
        }
        float hnew[8][4];
#pragma unroll
        for (int jt = 0; jt < 8; jt++) {
            float gq[4] = {gin[jt].x, gin[jt].y, gin[jt].z, gin[jt].w};
#pragma unroll
            for (int q = 0; q < 4; q++) {
                float r = sigf(acc[jt][q]);
                float z = sigf(acc[jt + 8][q]);
                float n = tanhf(gq[q] + r * acc[jt + 16][q]);
                float hv = (1.f - z) * n + z * hold[jt][q];
                hnew[jt][q] = hv;
                hold[jt][q] = hv;
            }
        }
        __syncwarp();
#pragma unroll
        for (int jt = 0; jt < 8; jt++) {
            *(float2*)(hw + g * 68 + jt * 8 + tg * 2) =
                make_float2(hnew[jt][0], hnew[jt][1]);
            *(float2*)(hw + (g + 8) * 68 + jt * 8 + tg * 2) =
                make_float2(hnew[jt][2], hnew[jt][3]);
        }
        __syncwarp();
        const float* hrow = hw + sl * 68 + ch;
        const float* fw = fwrow + l * 64;
#pragma unroll
        for (int u = 0; u < 8; u++) {
            float4 hh = *(const float4*)(hrow + u * 4);
            float4 wf = *(const float4*)(fw + u * 4);
            fcacc += hh.x * wf.x + hh.y * wf.y + hh.z * wf.z + hh.w * wf.w;
        }
    }

#pragma unroll
    for (int o = 16; o > 0; o >>= 1)
        fcacc += __shfl_down_sync(0xffffffffu, fcacc, o);
    if (lid == 0) g_part[blockIdx.x * 4 + ws] = fcacc;
}

// ---------------------------------------------------------------------------
__global__ void k3_fc(const float* __restrict__ fc_b, float* __restrict__ out) {
    int b = threadIdx.x;
    float s = fc_b[0];
#pragma unroll
    for (int k = 0; k < 4; k++) s += g_part[b * 4 + k];
    out[b] = s;
}

// ---------------------------------------------------------------------------
extern "C" void kernel_launch(void* const* d_in, const int* in_sizes, int n_in,
                              void* d_out, int out_size) {
    const float* x    = (const float*)d_in[0];
    const float* filt = (const float*)d_in[1];
    const float* w_ih = (const float*)d_in[2];
    const float* w_hh = (const float*)d_in[3];
    const float* b_ih = (const float*)d_in[4];
    const float* b_hh = (const float*)d_in[5];
    const float* fc_w = (const float*)d_in[6];
    const float* fc_b = (const float*)d_in[7];
    float* out = (float*)d_out;

    cudaFuncSetAttribute(k1_fused, cudaFuncAttributeMaxDynamicSharedMemorySize, SMEM1);
    cudaFuncSetAttribute(k2b_gru, cudaFuncAttributeMaxDynamicSharedMemorySize, SMEMB);

    k0_prepG<<<3, 192>>>(filt, w_ih);
    k0b_pack<<<24, 256>>>(b_ih, b_hh);
    k1_fused<<<8192, 256, SMEM1>>>(x);
    k2b_gru<<<256, 128, SMEMB>>>(w_hh, b_hh, fc_w);
    k3_fc<<<1, 256>>>(fc_b, out);
}